// round 7
// baseline (speedup 1.0000x reference)
#include <cuda_runtime.h>
#include <cuda_bf16.h>
#include <cstdint>
#include <math.h>

// Problem constants
#define BB   4
#define TT   2048
#define CC   1024
#define HH   16
#define DD   64
#define MTOT (BB*TT)          // 8192
#define NQKV (3*CC)           // 3072

typedef unsigned long long u64;
typedef unsigned int u32;

// ---------------------------------------------------------------------------
// Scratch in device globals (no allocations allowed)
// ---------------------------------------------------------------------------
__device__ float g_Q[(size_t)BB*HH*TT*DD];
__device__ float g_K[(size_t)BB*HH*TT*DD];
__device__ float g_V[(size_t)BB*HH*TT*DD];
// bf16 split buffers
__device__ __nv_bfloat16 g_xh[(size_t)MTOT*CC], g_xl[(size_t)MTOT*CC];
__device__ __nv_bfloat16 g_wqh[(size_t)NQKV*CC], g_wql[(size_t)NQKV*CC];
__device__ __nv_bfloat16 g_woh[(size_t)CC*CC],   g_wol[(size_t)CC*CC];
__device__ __nv_bfloat16 g_Oh[(size_t)MTOT*CC],  g_Ol[(size_t)MTOT*CC];

// ---------------------------------------------------------------------------
// Ampere-era PTX helpers (valid on plain sm_103 target: no 'a' features)
// ---------------------------------------------------------------------------
__device__ __forceinline__ void cp_async16(u32 saddr, const void* gaddr) {
    asm volatile("cp.async.cg.shared.global [%0], [%1], 16;"
                 :: "r"(saddr), "l"(gaddr));
}
__device__ __forceinline__ void cp_commit() {
    asm volatile("cp.async.commit_group;");
}
template<int N>
__device__ __forceinline__ void cp_wait() {
    asm volatile("cp.async.wait_group %0;" :: "n"(N));
}
__device__ __forceinline__ void ldsm_x4(u32* r, u32 addr) {
    asm volatile("ldmatrix.sync.aligned.m8n8.x4.shared.b16 {%0,%1,%2,%3}, [%4];"
                 : "=r"(r[0]), "=r"(r[1]), "=r"(r[2]), "=r"(r[3]) : "r"(addr));
}
__device__ __forceinline__ void ldsm_x2(u32* r, u32 addr) {
    asm volatile("ldmatrix.sync.aligned.m8n8.x2.shared.b16 {%0,%1}, [%2];"
                 : "=r"(r[0]), "=r"(r[1]) : "r"(addr));
}
__device__ __forceinline__ void mma16816(float* d, const u32* a, const u32* b) {
    asm volatile(
        "mma.sync.aligned.m16n8k16.row.col.f32.bf16.bf16.f32 "
        "{%0,%1,%2,%3}, {%4,%5,%6,%7}, {%8,%9}, {%0,%1,%2,%3};"
        : "+f"(d[0]), "+f"(d[1]), "+f"(d[2]), "+f"(d[3])
        : "r"(a[0]), "r"(a[1]), "r"(a[2]), "r"(a[3]), "r"(b[0]), "r"(b[1]));
}

// ---------------------------------------------------------------------------
// fp32 -> bf16 hi/lo split conversion (x, w_qkv, w_out)
// ---------------------------------------------------------------------------
__device__ __forceinline__ void split4(float4 v, uint2& H, uint2& L) {
    __nv_bfloat16 h0 = __float2bfloat16(v.x), h1 = __float2bfloat16(v.y);
    __nv_bfloat16 h2 = __float2bfloat16(v.z), h3 = __float2bfloat16(v.w);
    float e0 = v.x - __bfloat162float(h0), e1 = v.y - __bfloat162float(h1);
    float e2 = v.z - __bfloat162float(h2), e3 = v.w - __bfloat162float(h3);
    __nv_bfloat16 l0 = __float2bfloat16(e0), l1 = __float2bfloat16(e1);
    __nv_bfloat16 l2 = __float2bfloat16(e2), l3 = __float2bfloat16(e3);
    H.x = (u32)__bfloat16_as_ushort(h0) | ((u32)__bfloat16_as_ushort(h1) << 16);
    H.y = (u32)__bfloat16_as_ushort(h2) | ((u32)__bfloat16_as_ushort(h3) << 16);
    L.x = (u32)__bfloat16_as_ushort(l0) | ((u32)__bfloat16_as_ushort(l1) << 16);
    L.y = (u32)__bfloat16_as_ushort(l2) | ((u32)__bfloat16_as_ushort(l3) << 16);
}

__global__ __launch_bounds__(256)
void cvt_split(const float4* __restrict__ src, int which)
{
    size_t i = (size_t)blockIdx.x * 256 + threadIdx.x;
    float4 v = src[i];
    uint2 H, L;
    split4(v, H, L);
    uint2* hp; uint2* lp;
    if (which == 0)      { hp = (uint2*)g_xh;  lp = (uint2*)g_xl;  }
    else if (which == 1) { hp = (uint2*)g_wqh; lp = (uint2*)g_wql; }
    else                 { hp = (uint2*)g_woh; lp = (uint2*)g_wol; }
    hp[i] = H; lp[i] = L;
}

// ---------------------------------------------------------------------------
// mma.sync GEMM (NT): C[m,n] = sum_k A[m,k]*B[n,k], bf16 split-3, fp32 acc.
// 128x128 CTA tile, 8 warps (64x32 each), K-tile 32, cp.async double buffer.
// smem tile rows: 64B (32 bf16), 16B chunks swizzled by key=(row^row>>2)&3.
// EPI==0: A=x(hi/lo), B=w_qkv(hi/lo) -> scatter g_Q(*0.125)/g_K/g_V [B,H,T,D]
// EPI==1: A=g_O(hi/lo), B=w_out(hi/lo) -> row-major Cout
// ---------------------------------------------------------------------------
#define STAGE_BYTES 32768     // 4 tiles (Ah, Al, Bh, Bl) x 8KB
#define TILE_BYTES  8192
#define GSMEM (2 * STAGE_BYTES)

__device__ __forceinline__ u32 swz_off(int row, int chunk) {
    int key = (row ^ (row >> 2)) & 3;
    return (u32)(row * 64 + ((chunk ^ key) << 4));
}

template<int EPI>
__global__ __launch_bounds__(256)
void mma_gemm(float* __restrict__ Cout)
{
    extern __shared__ char smem[];
    const u32 sb = (u32)__cvta_generic_to_shared(smem);
    const int tid = threadIdx.x;
    const int wid = tid >> 5, lane = tid & 31;
    const int bn = blockIdx.x, bm = blockIdx.y;

    const __nv_bfloat16* Ah = EPI ? g_Oh : g_xh;
    const __nv_bfloat16* Al = EPI ? g_Ol : g_xl;
    const __nv_bfloat16* Bh = EPI ? g_woh : g_wqh;
    const __nv_bfloat16* Bl = EPI ? g_wol : g_wql;

    const int arow = bm * 128, brow = bn * 128;

    // Load mapping: idx = tid + i*256 (0..511); row = idx>>2, chunk = idx&3
    const int lrow = tid >> 2, lchunk = tid & 3;

    // Issue loads for k-block kb into stage st
    auto issue = [&](int kb, int st) {
        const int kcol = kb * 32 + lchunk * 8;
        u32 base = sb + st * STAGE_BYTES;
#pragma unroll
        for (int i = 0; i < 2; i++) {
            int row = lrow + i * 64;
            u32 so = swz_off(row, lchunk);
            size_t ga = (size_t)(arow + row) * CC + kcol;
            size_t gb = (size_t)(brow + row) * CC + kcol;
            cp_async16(base + so,                  Ah + ga);
            cp_async16(base + TILE_BYTES + so,     Al + ga);
            cp_async16(base + 2 * TILE_BYTES + so, Bh + gb);
            cp_async16(base + 3 * TILE_BYTES + so, Bl + gb);
        }
        cp_commit();
    };

    // Warp tiling: wm in {0,1} (64 rows), wn in {0..3} (32 cols)
    const int wm = wid & 1, wn = wid >> 1;

    // Precompute ldmatrix lane addresses for ks=0, stage 0.
    // A (x4): mat = lane>>3, sr = lane&7; row = wm*64 + mt*16 + sr + (mat&1)*8
    //         chunk = (mat>>1)
    // B (x2): l = lane&15; row = wn*32 + nt*8 + (l&7); chunk = (l>>3)
    u32 aaddr0[4], baddr0[4];
    {
        int mat = lane >> 3, sr = lane & 7;
        int arow_l = wm * 64 + sr + (mat & 1) * 8;
        int achunk = mat >> 1;
#pragma unroll
        for (int mt = 0; mt < 4; mt++)
            aaddr0[mt] = sb + swz_off(arow_l + mt * 16, achunk);
        int l = lane & 15;
        int brow_l = wn * 32 + (l & 7);
        int bchunk = l >> 3;
#pragma unroll
        for (int nt = 0; nt < 4; nt++)
            baddr0[nt] = sb + 2 * TILE_BYTES + swz_off(brow_l + nt * 8, bchunk);
    }

    float acc[4][4][4];
#pragma unroll
    for (int mt = 0; mt < 4; mt++)
#pragma unroll
        for (int nt = 0; nt < 4; nt++)
#pragma unroll
            for (int e = 0; e < 4; e++) acc[mt][nt][e] = 0.f;

    const int nk = CC / 32;      // 32 k-blocks

    issue(0, 0);

    for (int kb = 0; kb < nk; kb++) {
        const int st = kb & 1;
        if (kb + 1 < nk) {
            issue(kb + 1, st ^ 1);
            cp_wait<1>();
        } else {
            cp_wait<0>();
        }
        __syncthreads();

        const u32 soff = (u32)(st * STAGE_BYTES);
#pragma unroll
        for (int ks = 0; ks < 2; ks++) {
            const u32 kx = (u32)(ks << 5);
            u32 ahi[4][4], alo[4][4], bhi[4][2], blo[4][2];
#pragma unroll
            for (int mt = 0; mt < 4; mt++) {
                u32 ad = (aaddr0[mt] + soff) ^ kx;
                ldsm_x4(ahi[mt], ad);
                ldsm_x4(alo[mt], ad + TILE_BYTES);
            }
#pragma unroll
            for (int nt = 0; nt < 4; nt++) {
                u32 bd = (baddr0[nt] + soff) ^ kx;
                ldsm_x2(bhi[nt], bd);
                ldsm_x2(blo[nt], bd + TILE_BYTES);
            }
#pragma unroll
            for (int mt = 0; mt < 4; mt++) {
#pragma unroll
                for (int nt = 0; nt < 4; nt++) {
                    mma16816(acc[mt][nt], ahi[mt], bhi[nt]);
                    mma16816(acc[mt][nt], ahi[mt], blo[nt]);
                    mma16816(acc[mt][nt], alo[mt], bhi[nt]);
                }
            }
        }
        __syncthreads();
    }

    // Epilogue. Thread lane: gid = lane>>2 (row), tig = lane&3 (col pair)
    const int gid = lane >> 2, tig = lane & 3;
#pragma unroll
    for (int mt = 0; mt < 4; mt++) {
#pragma unroll
        for (int half = 0; half < 2; half++) {
            int m = bm * 128 + wm * 64 + mt * 16 + gid + half * 8;
#pragma unroll
            for (int nt = 0; nt < 4; nt++) {
                float c0 = acc[mt][nt][half * 2 + 0];
                float c1 = acc[mt][nt][half * 2 + 1];
                int n = bn * 128 + wn * 32 + nt * 8 + 2 * tig;
                if (EPI == 0) {
                    int sec = n >> 10, cn = n & 1023;
                    int h = cn >> 6, d = cn & 63;
                    int b = m >> 11, t = m & 2047;
                    float* dst;
                    if (sec == 0) { c0 *= 0.125f; c1 *= 0.125f; dst = g_Q; }
                    else if (sec == 1) dst = g_K;
                    else               dst = g_V;
                    *(float2*)&dst[(((size_t)(b * HH + h)) * TT + t) * DD + d] =
                        make_float2(c0, c1);
                } else {
                    *(float2*)&Cout[(size_t)m * CC + n] = make_float2(c0, c1);
                }
            }
        }
    }
}

// ---------------------------------------------------------------------------
// Packed f32x2 helpers
// ---------------------------------------------------------------------------
__device__ __forceinline__ u64 pk2d(float x) {
    u64 r; unsigned u = __float_as_uint(x);
    asm("mov.b64 %0, {%1, %1};" : "=l"(r) : "r"(u));
    return r;
}
__device__ __forceinline__ void fma2(u64& d, u64 a, u64 b) {
    asm("fma.rn.f32x2 %0, %1, %2, %0;" : "+l"(d) : "l"(a), "l"(b));
}
__device__ __forceinline__ void mul2(u64& d, u64 a) {
    asm("mul.rn.f32x2 %0, %0, %1;" : "+l"(d) : "l"(a));
}
__device__ __forceinline__ void up2(u64 v, float& x, float& y) {
    unsigned a, b;
    asm("mov.b64 {%0, %1}, %2;" : "=r"(a), "=r"(b) : "l"(v));
    x = __uint_as_float(a); y = __uint_as_float(b);
}

// ---------------------------------------------------------------------------
// Flash attention (causal), fp32 f32x2. Epilogue emits bf16 hi/lo for out-proj.
// ---------------------------------------------------------------------------
#define ATS 68
#define ATT_SMEM_FLOATS (4 * 64 * ATS)

__global__ __launch_bounds__(256)
void flash_attn_kernel()
{
    extern __shared__ float sm[];
    float* Qt = sm;                 // [64][68]  Qt[d][r]
    float* Kt = sm + 64 * ATS;      // [64][68]  Kt[d][c]
    float* Vs = sm + 2 * 64 * ATS;  // [64][68]  Vs[c][d]
    float* Pt = sm + 3 * 64 * ATS;  // [64][68]  Pt[c][r]

    const int b = blockIdx.z, h = blockIdx.y, qb = blockIdx.x;
    const int tid = threadIdx.x;
    const size_t hb = ((size_t)(b * HH + h)) * TT * DD;
    const float* Qg = g_Q + hb + (size_t)qb * 64 * DD;
    const float* Kg = g_K + hb;
    const float* Vg = g_V + hb;

    const int lcol  = tid & 63;
    const int dbase = (tid >> 6) * 16;

#pragma unroll
    for (int u = 0; u < 4; u++) {
        int d4 = dbase + 4 * u;
        float4 q4 = *(const float4*)&Qg[lcol * 64 + d4];
        Qt[(d4 + 0) * ATS + lcol] = q4.x;
        Qt[(d4 + 1) * ATS + lcol] = q4.y;
        Qt[(d4 + 2) * ATS + lcol] = q4.z;
        Qt[(d4 + 3) * ATS + lcol] = q4.w;
    }

    const int tx = tid & 15, ty = tid >> 4;
    const int r0 = ty * 4;
    const int c0 = tx * 4;

    float m_i[4], l_i[4];
    u64 o2[4][2];
#pragma unroll
    for (int i = 0; i < 4; i++) {
        m_i[i] = -INFINITY; l_i[i] = 0.f;
        o2[i][0] = 0ull; o2[i][1] = 0ull;
    }

    for (int j = 0; j <= qb; j++) {
        __syncthreads();
        const float* Kj = Kg + (size_t)j * 64 * DD;
        const float* Vj = Vg + (size_t)j * 64 * DD;
#pragma unroll
        for (int u = 0; u < 4; u++) {
            int d4 = dbase + 4 * u;
            float4 k4 = *(const float4*)&Kj[lcol * 64 + d4];
            Kt[(d4 + 0) * ATS + lcol] = k4.x;
            Kt[(d4 + 1) * ATS + lcol] = k4.y;
            Kt[(d4 + 2) * ATS + lcol] = k4.z;
            Kt[(d4 + 3) * ATS + lcol] = k4.w;
        }
#pragma unroll
        for (int u = 0; u < 4; u++) {
            int idx = tid + u * 256;
            int rr = idx >> 4, c4 = (idx & 15) * 4;
            *(float4*)&Vs[rr * ATS + c4] = *(const float4*)&Vj[rr * 64 + c4];
        }
        __syncthreads();

        u64 s2[4][2];
#pragma unroll
        for (int i = 0; i < 4; i++) { s2[i][0] = 0ull; s2[i][1] = 0ull; }
#pragma unroll 16
        for (int d = 0; d < 64; d++) {
            float4 a4 = *(const float4*)&Qt[d * ATS + r0];
            ulonglong2 k2 = *(const ulonglong2*)&Kt[d * ATS + c0];
            u64 aa;
            aa = pk2d(a4.x); fma2(s2[0][0], aa, k2.x); fma2(s2[0][1], aa, k2.y);
            aa = pk2d(a4.y); fma2(s2[1][0], aa, k2.x); fma2(s2[1][1], aa, k2.y);
            aa = pk2d(a4.z); fma2(s2[2][0], aa, k2.x); fma2(s2[2][1], aa, k2.y);
            aa = pk2d(a4.w); fma2(s2[3][0], aa, k2.x); fma2(s2[3][1], aa, k2.y);
        }

        float s[4][4];
#pragma unroll
        for (int i = 0; i < 4; i++) {
            up2(s2[i][0], s[i][0], s[i][1]);
            up2(s2[i][1], s[i][2], s[i][3]);
        }
        if (j == qb) {
#pragma unroll
            for (int i = 0; i < 4; i++)
#pragma unroll
                for (int cc = 0; cc < 4; cc++)
                    if (c0 + cc > r0 + i) s[i][cc] = -INFINITY;
        }
#pragma unroll
        for (int i = 0; i < 4; i++) {
            float mloc = fmaxf(fmaxf(s[i][0], s[i][1]), fmaxf(s[i][2], s[i][3]));
            mloc = fmaxf(mloc, __shfl_xor_sync(0xffffffffu, mloc, 1));
            mloc = fmaxf(mloc, __shfl_xor_sync(0xffffffffu, mloc, 2));
            mloc = fmaxf(mloc, __shfl_xor_sync(0xffffffffu, mloc, 4));
            mloc = fmaxf(mloc, __shfl_xor_sync(0xffffffffu, mloc, 8));
            float mnew = fmaxf(m_i[i], mloc);
            float al = __expf(m_i[i] - mnew);
            float ps = 0.f;
#pragma unroll
            for (int cc = 0; cc < 4; cc++) {
                float p = __expf(s[i][cc] - mnew);
                s[i][cc] = p;
                ps += p;
            }
            ps += __shfl_xor_sync(0xffffffffu, ps, 1);
            ps += __shfl_xor_sync(0xffffffffu, ps, 2);
            ps += __shfl_xor_sync(0xffffffffu, ps, 4);
            ps += __shfl_xor_sync(0xffffffffu, ps, 8);
            l_i[i] = al * l_i[i] + ps;
            m_i[i] = mnew;
            u64 al2 = pk2d(al);
            mul2(o2[i][0], al2);
            mul2(o2[i][1], al2);
        }
#pragma unroll
        for (int cc = 0; cc < 4; cc++) {
            float4 p4 = make_float4(s[0][cc], s[1][cc], s[2][cc], s[3][cc]);
            *(float4*)&Pt[(c0 + cc) * ATS + r0] = p4;
        }
        __syncthreads();

#pragma unroll 16
        for (int c = 0; c < 64; c++) {
            float4 p4 = *(const float4*)&Pt[c * ATS + r0];
            ulonglong2 v2 = *(const ulonglong2*)&Vs[c * ATS + c0];
            u64 aa;
            aa = pk2d(p4.x); fma2(o2[0][0], aa, v2.x); fma2(o2[0][1], aa, v2.y);
            aa = pk2d(p4.y); fma2(o2[1][0], aa, v2.x); fma2(o2[1][1], aa, v2.y);
            aa = pk2d(p4.z); fma2(o2[2][0], aa, v2.x); fma2(o2[2][1], aa, v2.y);
            aa = pk2d(p4.w); fma2(o2[3][0], aa, v2.x); fma2(o2[3][1], aa, v2.y);
        }
    }

    // epilogue: normalize and emit bf16 hi/lo into g_Oh/g_Ol  [B*T, C]
#pragma unroll
    for (int i = 0; i < 4; i++) {
        float inv = 1.f / l_i[i];
        float x0, y0, x1, y1;
        up2(o2[i][0], x0, y0);
        up2(o2[i][1], x1, y1);
        float4 v = make_float4(x0 * inv, y0 * inv, x1 * inv, y1 * inv);
        int rr = qb * 64 + r0 + i;
        size_t base = ((size_t)(b * TT + rr)) * CC + h * DD + c0;
        uint2 H, L;
        split4(v, H, L);
        *(uint2*)&g_Oh[base] = H;
        *(uint2*)&g_Ol[base] = L;
    }
}

// ---------------------------------------------------------------------------
extern "C" void kernel_launch(void* const* d_in, const int* in_sizes, int n_in,
                              void* d_out, int out_size)
{
    const float* x     = (const float*)d_in[0];
    // d_in[1] = mask (bool) — causal, applied analytically
    const float* w_qkv = (const float*)d_in[2];
    const float* w_out = (const float*)d_in[3];
    float* out = (float*)d_out;

    // 0) split inputs into bf16 hi/lo
    cvt_split<<<(MTOT * CC / 4) / 256, 256>>>((const float4*)x, 0);
    cvt_split<<<(NQKV * CC / 4) / 256, 256>>>((const float4*)w_qkv, 1);
    cvt_split<<<(CC * CC / 4) / 256, 256>>>((const float4*)w_out, 2);

    // 1) QKV projection via mma.sync -> g_Q (scaled), g_K, g_V
    cudaFuncSetAttribute(mma_gemm<0>, cudaFuncAttributeMaxDynamicSharedMemorySize,
                         GSMEM);
    mma_gemm<0><<<dim3(NQKV / 128, MTOT / 128), 256, GSMEM>>>(nullptr);

    // 2) causal flash attention -> g_Oh/g_Ol
    cudaFuncSetAttribute(flash_attn_kernel,
                         cudaFuncAttributeMaxDynamicSharedMemorySize,
                         ATT_SMEM_FLOATS * (int)sizeof(float));
    dim3 agrid(TT / 64, HH, BB);
    flash_attn_kernel<<<agrid, 256, ATT_SMEM_FLOATS * sizeof(float)>>>();

    // 3) output projection via mma.sync -> d_out
    cudaFuncSetAttribute(mma_gemm<1>, cudaFuncAttributeMaxDynamicSharedMemorySize,
                         GSMEM);
    mma_gemm<1><<<dim3(CC / 128, MTOT / 128), 256, GSMEM>>>(out);
}

// round 8
// speedup vs baseline: 2.7482x; 2.7482x over previous
#include <cuda_runtime.h>
#include <cuda_bf16.h>
#include <cstdint>
#include <math.h>

// Problem constants
#define BB   4
#define TT   2048
#define CC   1024
#define HH   16
#define DD   64
#define MTOT (BB*TT)          // 8192
#define NQKV (3*CC)           // 3072

typedef unsigned long long u64;
typedef unsigned int u32;

// ---------------------------------------------------------------------------
// Scratch in device globals (no allocations allowed)
// ---------------------------------------------------------------------------
__device__ __nv_bfloat16 g_xh[(size_t)MTOT*CC], g_xl[(size_t)MTOT*CC];
__device__ __nv_bfloat16 g_wqh[(size_t)NQKV*CC], g_wql[(size_t)NQKV*CC];
__device__ __nv_bfloat16 g_woh[(size_t)CC*CC],   g_wol[(size_t)CC*CC];
__device__ __nv_bfloat16 g_Oh[(size_t)MTOT*CC],  g_Ol[(size_t)MTOT*CC];
// QKV outputs as bf16 hi/lo, [B,H,T,D]
__device__ __nv_bfloat16 g_Qh[(size_t)BB*HH*TT*DD], g_Ql[(size_t)BB*HH*TT*DD];
__device__ __nv_bfloat16 g_Kh[(size_t)BB*HH*TT*DD], g_Kl[(size_t)BB*HH*TT*DD];
__device__ __nv_bfloat16 g_Vh[(size_t)BB*HH*TT*DD], g_Vl[(size_t)BB*HH*TT*DD];

// ---------------------------------------------------------------------------
// Ampere-era PTX helpers (valid on plain sm_103 target)
// ---------------------------------------------------------------------------
__device__ __forceinline__ void cp_async16(u32 saddr, const void* gaddr) {
    asm volatile("cp.async.cg.shared.global [%0], [%1], 16;"
                 :: "r"(saddr), "l"(gaddr));
}
__device__ __forceinline__ void cp_commit() {
    asm volatile("cp.async.commit_group;");
}
template<int N>
__device__ __forceinline__ void cp_wait() {
    asm volatile("cp.async.wait_group %0;" :: "n"(N));
}
__device__ __forceinline__ void ldsm_x4(u32* r, u32 addr) {
    asm volatile("ldmatrix.sync.aligned.m8n8.x4.shared.b16 {%0,%1,%2,%3}, [%4];"
                 : "=r"(r[0]), "=r"(r[1]), "=r"(r[2]), "=r"(r[3]) : "r"(addr));
}
__device__ __forceinline__ void ldsm_x4_t(u32* r, u32 addr) {
    asm volatile("ldmatrix.sync.aligned.m8n8.x4.trans.shared.b16 {%0,%1,%2,%3}, [%4];"
                 : "=r"(r[0]), "=r"(r[1]), "=r"(r[2]), "=r"(r[3]) : "r"(addr));
}
__device__ __forceinline__ void ldsm_x2(u32* r, u32 addr) {
    asm volatile("ldmatrix.sync.aligned.m8n8.x2.shared.b16 {%0,%1}, [%2];"
                 : "=r"(r[0]), "=r"(r[1]) : "r"(addr));
}
__device__ __forceinline__ void mma16816(float* d, const u32* a, const u32* b) {
    asm volatile(
        "mma.sync.aligned.m16n8k16.row.col.f32.bf16.bf16.f32 "
        "{%0,%1,%2,%3}, {%4,%5,%6,%7}, {%8,%9}, {%0,%1,%2,%3};"
        : "+f"(d[0]), "+f"(d[1]), "+f"(d[2]), "+f"(d[3])
        : "r"(a[0]), "r"(a[1]), "r"(a[2]), "r"(a[3]), "r"(b[0]), "r"(b[1]));
}

// fp32 pair -> packed bf16 hi / lo
__device__ __forceinline__ void split2u(float x, float y, u32& H, u32& L) {
    __nv_bfloat16 hx = __float2bfloat16(x), hy = __float2bfloat16(y);
    float ex = x - __bfloat162float(hx);
    float ey = y - __bfloat162float(hy);
    __nv_bfloat16 lx = __float2bfloat16(ex), ly = __float2bfloat16(ey);
    H = (u32)__bfloat16_as_ushort(hx) | ((u32)__bfloat16_as_ushort(hy) << 16);
    L = (u32)__bfloat16_as_ushort(lx) | ((u32)__bfloat16_as_ushort(ly) << 16);
}
__device__ __forceinline__ void split4(float4 v, uint2& H, uint2& L) {
    split2u(v.x, v.y, H.x, L.x);
    split2u(v.z, v.w, H.y, L.y);
}

// ---------------------------------------------------------------------------
// fp32 -> bf16 hi/lo split conversion (x, w_qkv, w_out)
// ---------------------------------------------------------------------------
__global__ __launch_bounds__(256)
void cvt_split(const float4* __restrict__ src, int which)
{
    size_t i = (size_t)blockIdx.x * 256 + threadIdx.x;
    float4 v = src[i];
    uint2 H, L;
    split4(v, H, L);
    uint2* hp; uint2* lp;
    if (which == 0)      { hp = (uint2*)g_xh;  lp = (uint2*)g_xl;  }
    else if (which == 1) { hp = (uint2*)g_wqh; lp = (uint2*)g_wql; }
    else                 { hp = (uint2*)g_woh; lp = (uint2*)g_wol; }
    hp[i] = H; lp[i] = L;
}

// ---------------------------------------------------------------------------
// mma.sync GEMM (NT): C[m,n] = sum_k A[m,k]*B[n,k], bf16 split-3, fp32 acc.
// EPI==0: -> g_Q*/g_K*/g_V* as bf16 hi/lo [B,H,T,D], Q scaled by 0.125
// EPI==1: A=g_O(hi/lo), B=w_out -> fp32 row-major Cout
// ---------------------------------------------------------------------------
#define STAGE_BYTES 32768
#define TILE_BYTES  8192
#define GSMEM (2 * STAGE_BYTES)

__device__ __forceinline__ u32 swz_off(int row, int chunk) {
    int key = (row ^ (row >> 2)) & 3;
    return (u32)(row * 64 + ((chunk ^ key) << 4));
}

template<int EPI>
__global__ __launch_bounds__(256)
void mma_gemm(float* __restrict__ Cout)
{
    extern __shared__ char smem[];
    const u32 sb = (u32)__cvta_generic_to_shared(smem);
    const int tid = threadIdx.x;
    const int wid = tid >> 5, lane = tid & 31;
    const int bn = blockIdx.x, bm = blockIdx.y;

    const __nv_bfloat16* Ah = EPI ? g_Oh : g_xh;
    const __nv_bfloat16* Al = EPI ? g_Ol : g_xl;
    const __nv_bfloat16* Bh = EPI ? g_woh : g_wqh;
    const __nv_bfloat16* Bl = EPI ? g_wol : g_wql;

    const int arow = bm * 128, brow = bn * 128;
    const int lrow = tid >> 2, lchunk = tid & 3;

    auto issue = [&](int kb, int st) {
        const int kcol = kb * 32 + lchunk * 8;
        u32 base = sb + st * STAGE_BYTES;
#pragma unroll
        for (int i = 0; i < 2; i++) {
            int row = lrow + i * 64;
            u32 so = swz_off(row, lchunk);
            size_t ga = (size_t)(arow + row) * CC + kcol;
            size_t gb = (size_t)(brow + row) * CC + kcol;
            cp_async16(base + so,                  Ah + ga);
            cp_async16(base + TILE_BYTES + so,     Al + ga);
            cp_async16(base + 2 * TILE_BYTES + so, Bh + gb);
            cp_async16(base + 3 * TILE_BYTES + so, Bl + gb);
        }
        cp_commit();
    };

    const int wm = wid & 1, wn = wid >> 1;

    u32 aaddr0[4], baddr0[4];
    {
        int mat = lane >> 3, sr = lane & 7;
        int arow_l = wm * 64 + sr + (mat & 1) * 8;
        int achunk = mat >> 1;
#pragma unroll
        for (int mt = 0; mt < 4; mt++)
            aaddr0[mt] = sb + swz_off(arow_l + mt * 16, achunk);
        int l = lane & 15;
        int brow_l = wn * 32 + (l & 7);
        int bchunk = l >> 3;
#pragma unroll
        for (int nt = 0; nt < 4; nt++)
            baddr0[nt] = sb + 2 * TILE_BYTES + swz_off(brow_l + nt * 8, bchunk);
    }

    float acc[4][4][4];
#pragma unroll
    for (int mt = 0; mt < 4; mt++)
#pragma unroll
        for (int nt = 0; nt < 4; nt++)
#pragma unroll
            for (int e = 0; e < 4; e++) acc[mt][nt][e] = 0.f;

    const int nk = CC / 32;
    issue(0, 0);

    for (int kb = 0; kb < nk; kb++) {
        const int st = kb & 1;
        if (kb + 1 < nk) { issue(kb + 1, st ^ 1); cp_wait<1>(); }
        else             { cp_wait<0>(); }
        __syncthreads();

        const u32 soff = (u32)(st * STAGE_BYTES);
#pragma unroll
        for (int ks = 0; ks < 2; ks++) {
            const u32 kx = (u32)(ks << 5);
            u32 ahi[4][4], alo[4][4], bhi[4][2], blo[4][2];
#pragma unroll
            for (int mt = 0; mt < 4; mt++) {
                u32 ad = (aaddr0[mt] + soff) ^ kx;
                ldsm_x4(ahi[mt], ad);
                ldsm_x4(alo[mt], ad + TILE_BYTES);
            }
#pragma unroll
            for (int nt = 0; nt < 4; nt++) {
                u32 bd = (baddr0[nt] + soff) ^ kx;
                ldsm_x2(bhi[nt], bd);
                ldsm_x2(blo[nt], bd + TILE_BYTES);
            }
#pragma unroll
            for (int mt = 0; mt < 4; mt++) {
#pragma unroll
                for (int nt = 0; nt < 4; nt++) {
                    mma16816(acc[mt][nt], ahi[mt], bhi[nt]);
                    mma16816(acc[mt][nt], ahi[mt], blo[nt]);
                    mma16816(acc[mt][nt], alo[mt], bhi[nt]);
                }
            }
        }
        __syncthreads();
    }

    const int gid = lane >> 2, tig = lane & 3;
#pragma unroll
    for (int mt = 0; mt < 4; mt++) {
#pragma unroll
        for (int half = 0; half < 2; half++) {
            int m = bm * 128 + wm * 64 + mt * 16 + gid + half * 8;
#pragma unroll
            for (int nt = 0; nt < 4; nt++) {
                float c0 = acc[mt][nt][half * 2 + 0];
                float c1 = acc[mt][nt][half * 2 + 1];
                int n = bn * 128 + wn * 32 + nt * 8 + 2 * tig;
                if (EPI == 0) {
                    int sec = n >> 10, cn = n & 1023;
                    int h = cn >> 6, d = cn & 63;
                    int b = m >> 11, t = m & 2047;
                    size_t idx = (((size_t)(b * HH + h)) * TT + t) * DD + d;
                    u32 H, L;
                    if (sec == 0) {
                        split2u(c0 * 0.125f, c1 * 0.125f, H, L);
                        *(u32*)&g_Qh[idx] = H; *(u32*)&g_Ql[idx] = L;
                    } else if (sec == 1) {
                        split2u(c0, c1, H, L);
                        *(u32*)&g_Kh[idx] = H; *(u32*)&g_Kl[idx] = L;
                    } else {
                        split2u(c0, c1, H, L);
                        *(u32*)&g_Vh[idx] = H; *(u32*)&g_Vl[idx] = L;
                    }
                } else {
                    *(float2*)&Cout[(size_t)m * CC + n] = make_float2(c0, c1);
                }
            }
        }
    }
}

// ---------------------------------------------------------------------------
// Flash attention (causal) via mma.sync bf16 3-MMA split.
// CTA: 128-query tile, 8 warps x 16 rows; key blocks of 64, cp.async
// double-buffered K/V (hi/lo). Warp-local online softmax. O in fp32.
// smem layout (bytes): Qh 0..16K, Ql 16K..32K, stage s at 32K+32K*s:
//   Kh +0, Kl +8K, Vh +16K, Vl +24K.  Total 96KB.
// ---------------------------------------------------------------------------
#define QTILE 128
#define KTILE 64
#define SQH 0
#define SQL 16384
#define SSTG(s) (32768 + (s) * 32768)
#define OKH 0
#define OKL 8192
#define OVH 16384
#define OVL 24576
#define ASMEM 98304

__device__ __forceinline__ u32 aswz(int row, int chunk) {
    return (u32)(row * 128 + ((chunk ^ (row & 7)) << 4));
}

__global__ __launch_bounds__(256)
void flash_attn_mma()
{
    extern __shared__ char smem[];
    const u32 sb = (u32)__cvta_generic_to_shared(smem);
    const int tid = threadIdx.x;
    const int wid = tid >> 5, lane = tid & 31;
    const int b = blockIdx.z, h = blockIdx.y;
    const int qb = gridDim.x - 1 - blockIdx.x;   // heavy tiles first
    const size_t hbase = (size_t)(b * HH + h) * TT * DD;
    const int qrow0 = qb * QTILE;
    const int nkb = 2 * qb + 2;

    // ---- cp.async issue: Q tile (hi/lo) ----
    {
#pragma unroll
        for (int i = 0; i < 8; i++) {
            int id = tid + i * 256;          // 0..2047
            int tens = id >> 10;             // 0 hi, 1 lo
            int rem = id & 1023;
            int row = rem >> 3, ch = rem & 7;
            const __nv_bfloat16* src =
                (tens ? g_Ql : g_Qh) + hbase + (size_t)(qrow0 + row) * DD + ch * 8;
            cp_async16(sb + (tens ? SQL : SQH) + aswz(row, ch), src);
        }
    }
    // ---- K/V stage issue ----
    auto issueKV = [&](int kb, int st) {
        u32 base = sb + SSTG(st);
        int t0 = kb * KTILE;
#pragma unroll
        for (int i = 0; i < 8; i++) {
            int id = tid + i * 256;          // 0..2047
            int tens = id >> 9;              // 0 Kh 1 Kl 2 Vh 3 Vl
            int rem = id & 511;
            int row = rem >> 3, ch = rem & 7;
            const __nv_bfloat16* src;
            u32 off;
            if (tens == 0)      { src = g_Kh; off = OKH; }
            else if (tens == 1) { src = g_Kl; off = OKL; }
            else if (tens == 2) { src = g_Vh; off = OVH; }
            else                { src = g_Vl; off = OVL; }
            cp_async16(base + off + aswz(row, ch),
                       src + hbase + (size_t)(t0 + row) * DD + ch * 8);
        }
    };

    issueKV(0, 0); cp_commit();           // group 0: Q + stage0
    issueKV(1, 1); cp_commit();           // group 1: stage1 (nkb >= 2 always)

    const int m0 = wid * 16;
    const int gid = lane >> 2, tig = lane & 3;
    const int r0g = qrow0 + m0 + gid;
    const int r1g = r0g + 8;

    u32 qh[4][4], ql[4][4];
    float o[8][4];
    float m_i0 = -INFINITY, m_i1 = -INFINITY, l_i0 = 0.f, l_i1 = 0.f;
#pragma unroll
    for (int n = 0; n < 8; n++)
#pragma unroll
        for (int e = 0; e < 4; e++) o[n][e] = 0.f;

    for (int kb = 0; kb < nkb; kb++) {
        if (kb + 1 < nkb) cp_wait<1>(); else cp_wait<0>();
        __syncthreads();

        if (kb == 0) {   // load Q fragments once
            int qrow = m0 + (lane & 15);
            int csel = lane >> 4;
#pragma unroll
            for (int ks = 0; ks < 4; ks++) {
                u32 ad = sb + SQH + aswz(qrow, 2 * ks + csel);
                ldsm_x4(qh[ks], ad);
                ldsm_x4(ql[ks], ad + (SQL - SQH));
            }
        }

        const u32 stg = sb + SSTG(kb & 1);

        // ---- S = Q K^T (16 x 64 per warp) ----
        float s[8][4];
#pragma unroll
        for (int j = 0; j < 8; j++) {
            s[j][0] = s[j][1] = s[j][2] = s[j][3] = 0.f;
            u32 kh[8], kl[8];
            int krow = 8 * j + (lane & 7);
            int kc = lane >> 3;              // 0..3
            ldsm_x4(kh,     stg + OKH + aswz(krow, kc));
            ldsm_x4(kh + 4, stg + OKH + aswz(krow, 4 + kc));
            ldsm_x4(kl,     stg + OKL + aswz(krow, kc));
            ldsm_x4(kl + 4, stg + OKL + aswz(krow, 4 + kc));
#pragma unroll
            for (int ks = 0; ks < 4; ks++) {
                mma16816(s[j], qh[ks], kh + 2 * ks);
                mma16816(s[j], qh[ks], kl + 2 * ks);
                mma16816(s[j], ql[ks], kh + 2 * ks);
            }
        }

        // ---- causal mask (only diagonal-region blocks) ----
        if (kb >= 2 * qb) {
#pragma unroll
            for (int j = 0; j < 8; j++) {
                int c = kb * KTILE + 8 * j + 2 * tig;
                if (c     > r0g) s[j][0] = -INFINITY;
                if (c + 1 > r0g) s[j][1] = -INFINITY;
                if (c     > r1g) s[j][2] = -INFINITY;
                if (c + 1 > r1g) s[j][3] = -INFINITY;
            }
        }

        // ---- online softmax (rows r0g, r1g; reduce over 4 quad lanes) ----
        float mx0 = -INFINITY, mx1 = -INFINITY;
#pragma unroll
        for (int j = 0; j < 8; j++) {
            mx0 = fmaxf(mx0, fmaxf(s[j][0], s[j][1]));
            mx1 = fmaxf(mx1, fmaxf(s[j][2], s[j][3]));
        }
        mx0 = fmaxf(mx0, __shfl_xor_sync(0xffffffffu, mx0, 1));
        mx0 = fmaxf(mx0, __shfl_xor_sync(0xffffffffu, mx0, 2));
        mx1 = fmaxf(mx1, __shfl_xor_sync(0xffffffffu, mx1, 1));
        mx1 = fmaxf(mx1, __shfl_xor_sync(0xffffffffu, mx1, 2));
        float mn0 = fmaxf(m_i0, mx0), mn1 = fmaxf(m_i1, mx1);
        float al0 = __expf(m_i0 - mn0), al1 = __expf(m_i1 - mn1);
        float sum0 = 0.f, sum1 = 0.f;
#pragma unroll
        for (int j = 0; j < 8; j++) {
            s[j][0] = __expf(s[j][0] - mn0);
            s[j][1] = __expf(s[j][1] - mn0);
            s[j][2] = __expf(s[j][2] - mn1);
            s[j][3] = __expf(s[j][3] - mn1);
            sum0 += s[j][0] + s[j][1];
            sum1 += s[j][2] + s[j][3];
        }
        sum0 += __shfl_xor_sync(0xffffffffu, sum0, 1);
        sum0 += __shfl_xor_sync(0xffffffffu, sum0, 2);
        sum1 += __shfl_xor_sync(0xffffffffu, sum1, 1);
        sum1 += __shfl_xor_sync(0xffffffffu, sum1, 2);
        l_i0 = al0 * l_i0 + sum0;  m_i0 = mn0;
        l_i1 = al1 * l_i1 + sum1;  m_i1 = mn1;
#pragma unroll
        for (int n = 0; n < 8; n++) {
            o[n][0] *= al0; o[n][1] *= al0;
            o[n][2] *= al1; o[n][3] *= al1;
        }

        // ---- P -> bf16 hi/lo A-fragments (register repack, FA2 style) ----
        u32 pah[4][4], pal[4][4];
#pragma unroll
        for (int ks = 0; ks < 4; ks++) {
            split2u(s[2*ks][0],   s[2*ks][1],   pah[ks][0], pal[ks][0]);
            split2u(s[2*ks][2],   s[2*ks][3],   pah[ks][1], pal[ks][1]);
            split2u(s[2*ks+1][0], s[2*ks+1][1], pah[ks][2], pal[ks][2]);
            split2u(s[2*ks+1][2], s[2*ks+1][3], pah[ks][3], pal[ks][3]);
        }

        // ---- O += P V  (V via ldmatrix.trans) ----
#pragma unroll
        for (int n = 0; n < 8; n++) {
            u32 vh[8], vl[8];
            ldsm_x4_t(vh,     stg + OVH + aswz(lane, n));
            ldsm_x4_t(vh + 4, stg + OVH + aswz(32 + lane, n));
            ldsm_x4_t(vl,     stg + OVL + aswz(lane, n));
            ldsm_x4_t(vl + 4, stg + OVL + aswz(32 + lane, n));
#pragma unroll
            for (int ks = 0; ks < 4; ks++) {
                mma16816(o[n], pah[ks], vh + 2 * ks);
                mma16816(o[n], pah[ks], vl + 2 * ks);
                mma16816(o[n], pal[ks], vh + 2 * ks);
            }
        }

        __syncthreads();
        if (kb + 2 < nkb) { issueKV(kb + 2, kb & 1); cp_commit(); }
    }

    // ---- epilogue: normalize, emit bf16 hi/lo into g_Oh/g_Ol [B*T, C] ----
    float inv0 = 1.f / l_i0, inv1 = 1.f / l_i1;
    int t0 = qrow0 + m0 + gid;
    size_t rb0 = ((size_t)(b * TT + t0)) * CC + h * DD;
    size_t rb1 = rb0 + (size_t)8 * CC;
#pragma unroll
    for (int n = 0; n < 8; n++) {
        u32 H, L;
        int coff = 8 * n + 2 * tig;
        split2u(o[n][0] * inv0, o[n][1] * inv0, H, L);
        *(u32*)&g_Oh[rb0 + coff] = H;
        *(u32*)&g_Ol[rb0 + coff] = L;
        split2u(o[n][2] * inv1, o[n][3] * inv1, H, L);
        *(u32*)&g_Oh[rb1 + coff] = H;
        *(u32*)&g_Ol[rb1 + coff] = L;
    }
}

// ---------------------------------------------------------------------------
extern "C" void kernel_launch(void* const* d_in, const int* in_sizes, int n_in,
                              void* d_out, int out_size)
{
    const float* x     = (const float*)d_in[0];
    // d_in[1] = mask (bool) — causal, applied analytically
    const float* w_qkv = (const float*)d_in[2];
    const float* w_out = (const float*)d_in[3];
    float* out = (float*)d_out;

    // 0) split inputs into bf16 hi/lo
    cvt_split<<<(MTOT * CC / 4) / 256, 256>>>((const float4*)x, 0);
    cvt_split<<<(NQKV * CC / 4) / 256, 256>>>((const float4*)w_qkv, 1);
    cvt_split<<<(CC * CC / 4) / 256, 256>>>((const float4*)w_out, 2);

    // 1) QKV projection via mma.sync -> bf16 hi/lo Q(scaled)/K/V
    cudaFuncSetAttribute(mma_gemm<0>, cudaFuncAttributeMaxDynamicSharedMemorySize,
                         GSMEM);
    mma_gemm<0><<<dim3(NQKV / 128, MTOT / 128), 256, GSMEM>>>(nullptr);

    // 2) causal flash attention (mma.sync) -> g_Oh/g_Ol
    cudaFuncSetAttribute(flash_attn_mma,
                         cudaFuncAttributeMaxDynamicSharedMemorySize, ASMEM);
    flash_attn_mma<<<dim3(TT / QTILE, HH, BB), 256, ASMEM>>>();

    // 3) output projection via mma.sync -> d_out
    cudaFuncSetAttribute(mma_gemm<1>, cudaFuncAttributeMaxDynamicSharedMemorySize,
                         GSMEM);
    mma_gemm<1><<<dim3(CC / 128, MTOT / 128), 256, GSMEM>>>(out);
}

// round 10
// speedup vs baseline: 3.4210x; 1.2448x over previous
#include <cuda_runtime.h>
#include <cuda_bf16.h>
#include <cuda_fp16.h>
#include <cstdint>
#include <math.h>

// Problem constants
#define BB   4
#define TT   2048
#define CC   1024
#define HH   16
#define DD   64
#define MTOT (BB*TT)          // 8192
#define NQKV (3*CC)           // 3072

typedef unsigned long long u64;
typedef unsigned int u32;

// ---------------------------------------------------------------------------
// Scratch in device globals (no allocations allowed)
// ---------------------------------------------------------------------------
__device__ __nv_bfloat16 g_xh[(size_t)MTOT*CC], g_xl[(size_t)MTOT*CC];
__device__ __nv_bfloat16 g_wqh[(size_t)NQKV*CC], g_wql[(size_t)NQKV*CC];
__device__ __nv_bfloat16 g_woh[(size_t)CC*CC],   g_wol[(size_t)CC*CC];
__device__ __nv_bfloat16 g_Oh[(size_t)MTOT*CC],  g_Ol[(size_t)MTOT*CC];
// QKV outputs as single fp16, [B,H,T,D]
__device__ __half g_Qf[(size_t)BB*HH*TT*DD];
__device__ __half g_Kf[(size_t)BB*HH*TT*DD];
__device__ __half g_Vf[(size_t)BB*HH*TT*DD];

// ---------------------------------------------------------------------------
// PTX helpers (plain sm_103 target)
// ---------------------------------------------------------------------------
__device__ __forceinline__ void cp_async16(u32 saddr, const void* gaddr) {
    asm volatile("cp.async.cg.shared.global [%0], [%1], 16;"
                 :: "r"(saddr), "l"(gaddr));
}
__device__ __forceinline__ void cp_commit() {
    asm volatile("cp.async.commit_group;");
}
template<int N>
__device__ __forceinline__ void cp_wait() {
    asm volatile("cp.async.wait_group %0;" :: "n"(N));
}
__device__ __forceinline__ void ldsm_x4(u32* r, u32 addr) {
    asm volatile("ldmatrix.sync.aligned.m8n8.x4.shared.b16 {%0,%1,%2,%3}, [%4];"
                 : "=r"(r[0]), "=r"(r[1]), "=r"(r[2]), "=r"(r[3]) : "r"(addr));
}
__device__ __forceinline__ void ldsm_x4_t(u32* r, u32 addr) {
    asm volatile("ldmatrix.sync.aligned.m8n8.x4.trans.shared.b16 {%0,%1,%2,%3}, [%4];"
                 : "=r"(r[0]), "=r"(r[1]), "=r"(r[2]), "=r"(r[3]) : "r"(addr));
}
__device__ __forceinline__ void mma16816(float* d, const u32* a, const u32* b) {
    asm volatile(
        "mma.sync.aligned.m16n8k16.row.col.f32.bf16.bf16.f32 "
        "{%0,%1,%2,%3}, {%4,%5,%6,%7}, {%8,%9}, {%0,%1,%2,%3};"
        : "+f"(d[0]), "+f"(d[1]), "+f"(d[2]), "+f"(d[3])
        : "r"(a[0]), "r"(a[1]), "r"(a[2]), "r"(a[3]), "r"(b[0]), "r"(b[1]));
}
__device__ __forceinline__ void mma16816h(float* d, const u32* a, const u32* b) {
    asm volatile(
        "mma.sync.aligned.m16n8k16.row.col.f32.f16.f16.f32 "
        "{%0,%1,%2,%3}, {%4,%5,%6,%7}, {%8,%9}, {%0,%1,%2,%3};"
        : "+f"(d[0]), "+f"(d[1]), "+f"(d[2]), "+f"(d[3])
        : "r"(a[0]), "r"(a[1]), "r"(a[2]), "r"(a[3]), "r"(b[0]), "r"(b[1]));
}

// fp32 pair -> packed bf16 hi / lo
__device__ __forceinline__ void split2u(float x, float y, u32& H, u32& L) {
    __nv_bfloat16 hx = __float2bfloat16(x), hy = __float2bfloat16(y);
    float ex = x - __bfloat162float(hx);
    float ey = y - __bfloat162float(hy);
    __nv_bfloat16 lx = __float2bfloat16(ex), ly = __float2bfloat16(ey);
    H = (u32)__bfloat16_as_ushort(hx) | ((u32)__bfloat16_as_ushort(hy) << 16);
    L = (u32)__bfloat16_as_ushort(lx) | ((u32)__bfloat16_as_ushort(ly) << 16);
}
__device__ __forceinline__ void split4(float4 v, uint2& H, uint2& L) {
    split2u(v.x, v.y, H.x, L.x);
    split2u(v.z, v.w, H.y, L.y);
}
__device__ __forceinline__ u32 packh2(float x, float y) {
    __half2 h = __floats2half2_rn(x, y);   // low=x, high=y
    return *(u32*)&h;
}

// ---------------------------------------------------------------------------
// fp32 -> bf16 hi/lo split conversion (x, w_qkv, w_out)
// ---------------------------------------------------------------------------
__global__ __launch_bounds__(256)
void cvt_split(const float4* __restrict__ src, int which)
{
    size_t i = (size_t)blockIdx.x * 256 + threadIdx.x;
    float4 v = src[i];
    uint2 H, L;
    split4(v, H, L);
    uint2* hp; uint2* lp;
    if (which == 0)      { hp = (uint2*)g_xh;  lp = (uint2*)g_xl;  }
    else if (which == 1) { hp = (uint2*)g_wqh; lp = (uint2*)g_wql; }
    else                 { hp = (uint2*)g_woh; lp = (uint2*)g_wol; }
    hp[i] = H; lp[i] = L;
}

// ---------------------------------------------------------------------------
// mma.sync GEMM (NT): C[m,n] = sum_k A[m,k]*B[n,k], bf16 split-3, fp32 acc.
// CTA tile 128x256, 8 warps as 2(wm) x 4(wn) -> 64x64 per warp.
// K-tile 32, cp.async double buffer.
// Stage layout: Ah @0 (8K), Al @8K, Bh @16K (16K), Bl @32K. Stage=48KB.
// EPI==0: -> g_Qf(*0.125)/g_Kf/g_Vf fp16 [B,H,T,D]
// EPI==1: A=g_O(hi/lo), B=w_out -> fp32 row-major Cout
// ---------------------------------------------------------------------------
#define STAGE_BYTES 49152
#define GSMEM (2 * STAGE_BYTES)

__device__ __forceinline__ u32 swz_off(int row, int chunk) {
    int key = (row ^ (row >> 2)) & 3;
    return (u32)(row * 64 + ((chunk ^ key) << 4));
}

template<int EPI>
__global__ __launch_bounds__(256)
void mma_gemm(float* __restrict__ Cout)
{
    extern __shared__ char smem[];
    const u32 sb = (u32)__cvta_generic_to_shared(smem);
    const int tid = threadIdx.x;
    const int wid = tid >> 5, lane = tid & 31;
    const int bn = blockIdx.x, bm = blockIdx.y;

    const __nv_bfloat16* Ah = EPI ? g_Oh : g_xh;
    const __nv_bfloat16* Al = EPI ? g_Ol : g_xl;
    const __nv_bfloat16* Bh = EPI ? g_woh : g_wqh;
    const __nv_bfloat16* Bl = EPI ? g_wol : g_wql;

    const int arow = bm * 128, brow = bn * 256;
    const int lrow = tid >> 2, lchunk = tid & 3;

    auto issue = [&](int kb, int st) {
        const int kcol = kb * 32 + lchunk * 8;
        u32 base = sb + st * STAGE_BYTES;
#pragma unroll
        for (int i = 0; i < 2; i++) {
            int row = lrow + i * 64;
            u32 so = swz_off(row, lchunk);
            size_t ga = (size_t)(arow + row) * CC + kcol;
            cp_async16(base + so,        Ah + ga);
            cp_async16(base + 8192 + so, Al + ga);
        }
#pragma unroll
        for (int j = 0; j < 4; j++) {
            int row = lrow + j * 64;
            u32 so = swz_off(row, lchunk);
            size_t gb = (size_t)(brow + row) * CC + kcol;
            cp_async16(base + 16384 + so, Bh + gb);
            cp_async16(base + 32768 + so, Bl + gb);
        }
        cp_commit();
    };

    const int wm = wid & 1, wn = wid >> 1;

    // ldmatrix base addresses (stage 0, ks 0)
    u32 aaddr0[4], baddr0[4];
    {
        int mat = lane >> 3, sr = lane & 7;
        int arow_l = wm * 64 + sr + (mat & 1) * 8;
        int achunk = mat >> 1;
#pragma unroll
        for (int mt = 0; mt < 4; mt++)
            aaddr0[mt] = sb + swz_off(arow_l + mt * 16, achunk);
        // B x4: g = lane>>3; matrices: (g>>1) selects n8-subtile, (g&1) = k-chunk
        int g = lane >> 3;
        int brow_l = wn * 64 + (g >> 1) * 8 + (lane & 7);
        int bchunk = g & 1;
#pragma unroll
        for (int ntp = 0; ntp < 4; ntp++)
            baddr0[ntp] = sb + 16384 + swz_off(brow_l + ntp * 16, bchunk);
    }

    float acc[4][8][4];
#pragma unroll
    for (int mt = 0; mt < 4; mt++)
#pragma unroll
        for (int nt = 0; nt < 8; nt++)
#pragma unroll
            for (int e = 0; e < 4; e++) acc[mt][nt][e] = 0.f;

    const int nk = CC / 32;
    issue(0, 0);

    for (int kb = 0; kb < nk; kb++) {
        const int st = kb & 1;
        if (kb + 1 < nk) { issue(kb + 1, st ^ 1); cp_wait<1>(); }
        else             { cp_wait<0>(); }
        __syncthreads();

        const u32 soff = (u32)(st * STAGE_BYTES);
#pragma unroll
        for (int ks = 0; ks < 2; ks++) {
            const u32 kx = (u32)(ks << 5);
            u32 ahi[4][4], alo[4][4];
#pragma unroll
            for (int mt = 0; mt < 4; mt++) {
                u32 ad = (aaddr0[mt] + soff) ^ kx;
                ldsm_x4(ahi[mt], ad);
                ldsm_x4(alo[mt], ad + 8192);
            }
#pragma unroll
            for (int ntp = 0; ntp < 4; ntp++) {
                u32 bh4[4], bl4[4];
                u32 bd = (baddr0[ntp] + soff) ^ kx;
                ldsm_x4(bh4, bd);
                ldsm_x4(bl4, bd + 16384);
#pragma unroll
                for (int mt = 0; mt < 4; mt++) {
                    mma16816(acc[mt][2*ntp],   ahi[mt], bh4);
                    mma16816(acc[mt][2*ntp],   ahi[mt], bl4);
                    mma16816(acc[mt][2*ntp],   alo[mt], bh4);
                    mma16816(acc[mt][2*ntp+1], ahi[mt], bh4 + 2);
                    mma16816(acc[mt][2*ntp+1], ahi[mt], bl4 + 2);
                    mma16816(acc[mt][2*ntp+1], alo[mt], bh4 + 2);
                }
            }
        }
        __syncthreads();
    }

    const int gid = lane >> 2, tig = lane & 3;
#pragma unroll
    for (int mt = 0; mt < 4; mt++) {
#pragma unroll
        for (int half = 0; half < 2; half++) {
            int m = bm * 128 + wm * 64 + mt * 16 + gid + half * 8;
#pragma unroll
            for (int nt = 0; nt < 8; nt++) {
                float c0 = acc[mt][nt][half * 2 + 0];
                float c1 = acc[mt][nt][half * 2 + 1];
                int n = bn * 256 + wn * 64 + nt * 8 + 2 * tig;
                if (EPI == 0) {
                    int sec = n >> 10, cn = n & 1023;
                    int h = cn >> 6, d = cn & 63;
                    int b = m >> 11, t = m & 2047;
                    size_t idx = (((size_t)(b * HH + h)) * TT + t) * DD + d;
                    __half* dst;
                    if (sec == 0) { c0 *= 0.125f; c1 *= 0.125f; dst = g_Qf; }
                    else if (sec == 1) dst = g_Kf;
                    else               dst = g_Vf;
                    *(u32*)&dst[idx] = packh2(c0, c1);
                } else {
                    *(float2*)&Cout[(size_t)m * CC + n] = make_float2(c0, c1);
                }
            }
        }
    }
}

// ---------------------------------------------------------------------------
// Flash attention (causal) via single-pass fp16 mma.sync.
// CTA: 128-query tile, 8 warps x 16 rows; key blocks of 64, cp.async
// double-buffered K/V. Warp-local online softmax. O in fp32.
// smem: Q @0 (16KB), stage s @16K+16K*s: K +0, V +8K. Total 48KB.
// ---------------------------------------------------------------------------
#define QTILE 128
#define KTILE 64
#define ASTG(s) (16384 + (s) * 16384)
#define OKOF 0
#define OVOF 8192
#define ASMEM 49152

__device__ __forceinline__ u32 aswz(int row, int chunk) {
    return (u32)(row * 128 + ((chunk ^ (row & 7)) << 4));
}

__global__ __launch_bounds__(256)
void flash_attn_fp16()
{
    extern __shared__ char smem[];
    const u32 sb = (u32)__cvta_generic_to_shared(smem);
    const int tid = threadIdx.x;
    const int wid = tid >> 5, lane = tid & 31;
    const int b = blockIdx.z, h = blockIdx.y;
    const int qb = gridDim.x - 1 - blockIdx.x;   // heavy tiles first
    const size_t hbase = (size_t)(b * HH + h) * TT * DD;
    const int qrow0 = qb * QTILE;
    const int nkb = 2 * qb + 2;

    // ---- Q tile (fp16): 1024 chunks, 4 per thread ----
#pragma unroll
    for (int i = 0; i < 4; i++) {
        int id = tid + i * 256;
        int row = id >> 3, ch = id & 7;
        cp_async16(sb + aswz(row, ch),
                   g_Qf + hbase + (size_t)(qrow0 + row) * DD + ch * 8);
    }
    // ---- K/V stage issue: 1024 chunks, 4 per thread ----
    auto issueKV = [&](int kb, int st) {
        u32 base = sb + ASTG(st);
        int t0 = kb * KTILE;
#pragma unroll
        for (int i = 0; i < 4; i++) {
            int id = tid + i * 256;
            int tens = id >> 9;              // 0 K, 1 V
            int rem = id & 511;
            int row = rem >> 3, ch = rem & 7;
            const __half* src = tens ? g_Vf : g_Kf;
            u32 off = tens ? OVOF : OKOF;
            cp_async16(base + off + aswz(row, ch),
                       src + hbase + (size_t)(t0 + row) * DD + ch * 8);
        }
    };

    issueKV(0, 0); cp_commit();           // group 0: Q + stage0
    issueKV(1, 1); cp_commit();           // group 1: stage1

    const int m0 = wid * 16;
    const int gid = lane >> 2, tig = lane & 3;
    const int r0g = qrow0 + m0 + gid;
    const int r1g = r0g + 8;

    u32 qf[4][4];
    float o[8][4];
    float m_i0 = -INFINITY, m_i1 = -INFINITY, l_i0 = 0.f, l_i1 = 0.f;
#pragma unroll
    for (int n = 0; n < 8; n++)
#pragma unroll
        for (int e = 0; e < 4; e++) o[n][e] = 0.f;

    for (int kb = 0; kb < nkb; kb++) {
        if (kb + 1 < nkb) cp_wait<1>(); else cp_wait<0>();
        __syncthreads();

        if (kb == 0) {   // load Q fragments once
            int qrow = m0 + (lane & 15);
            int csel = lane >> 4;
#pragma unroll
            for (int ks = 0; ks < 4; ks++)
                ldsm_x4(qf[ks], sb + aswz(qrow, 2 * ks + csel));
        }

        const u32 stg = sb + ASTG(kb & 1);

        // ---- S = Q K^T (16 x 64 per warp) ----
        float s[8][4];
#pragma unroll
        for (int j = 0; j < 8; j++) {
            s[j][0] = s[j][1] = s[j][2] = s[j][3] = 0.f;
            u32 kf[8];
            int krow = 8 * j + (lane & 7);
            int kc = lane >> 3;              // 0..3
            ldsm_x4(kf,     stg + OKOF + aswz(krow, kc));
            ldsm_x4(kf + 4, stg + OKOF + aswz(krow, 4 + kc));
#pragma unroll
            for (int ks = 0; ks < 4; ks++)
                mma16816h(s[j], qf[ks], kf + 2 * ks);
        }

        // ---- causal mask (diagonal-region blocks only) ----
        if (kb >= 2 * qb) {
#pragma unroll
            for (int j = 0; j < 8; j++) {
                int c = kb * KTILE + 8 * j + 2 * tig;
                if (c     > r0g) s[j][0] = -INFINITY;
                if (c + 1 > r0g) s[j][1] = -INFINITY;
                if (c     > r1g) s[j][2] = -INFINITY;
                if (c + 1 > r1g) s[j][3] = -INFINITY;
            }
        }

        // ---- online softmax (rows r0g, r1g; reduce over 4 quad lanes) ----
        float mx0 = -INFINITY, mx1 = -INFINITY;
#pragma unroll
        for (int j = 0; j < 8; j++) {
            mx0 = fmaxf(mx0, fmaxf(s[j][0], s[j][1]));
            mx1 = fmaxf(mx1, fmaxf(s[j][2], s[j][3]));
        }
        mx0 = fmaxf(mx0, __shfl_xor_sync(0xffffffffu, mx0, 1));
        mx0 = fmaxf(mx0, __shfl_xor_sync(0xffffffffu, mx0, 2));
        mx1 = fmaxf(mx1, __shfl_xor_sync(0xffffffffu, mx1, 1));
        mx1 = fmaxf(mx1, __shfl_xor_sync(0xffffffffu, mx1, 2));
        float mn0 = fmaxf(m_i0, mx0), mn1 = fmaxf(m_i1, mx1);
        float al0 = __expf(m_i0 - mn0), al1 = __expf(m_i1 - mn1);
        float sum0 = 0.f, sum1 = 0.f;
#pragma unroll
        for (int j = 0; j < 8; j++) {
            s[j][0] = __expf(s[j][0] - mn0);
            s[j][1] = __expf(s[j][1] - mn0);
            s[j][2] = __expf(s[j][2] - mn1);
            s[j][3] = __expf(s[j][3] - mn1);
            sum0 += s[j][0] + s[j][1];
            sum1 += s[j][2] + s[j][3];
        }
        sum0 += __shfl_xor_sync(0xffffffffu, sum0, 1);
        sum0 += __shfl_xor_sync(0xffffffffu, sum0, 2);
        sum1 += __shfl_xor_sync(0xffffffffu, sum1, 1);
        sum1 += __shfl_xor_sync(0xffffffffu, sum1, 2);
        l_i0 = al0 * l_i0 + sum0;  m_i0 = mn0;
        l_i1 = al1 * l_i1 + sum1;  m_i1 = mn1;
#pragma unroll
        for (int n = 0; n < 8; n++) {
            o[n][0] *= al0; o[n][1] *= al0;
            o[n][2] *= al1; o[n][3] *= al1;
        }

        // ---- P -> fp16 A-fragments (register repack) ----
        u32 pa[4][4];
#pragma unroll
        for (int ks = 0; ks < 4; ks++) {
            pa[ks][0] = packh2(s[2*ks][0],   s[2*ks][1]);
            pa[ks][1] = packh2(s[2*ks][2],   s[2*ks][3]);
            pa[ks][2] = packh2(s[2*ks+1][0], s[2*ks+1][1]);
            pa[ks][3] = packh2(s[2*ks+1][2], s[2*ks+1][3]);
        }

        // ---- O += P V  (V via ldmatrix.trans) ----
#pragma unroll
        for (int n = 0; n < 8; n++) {
            u32 vf[8];
            ldsm_x4_t(vf,     stg + OVOF + aswz(lane, n));
            ldsm_x4_t(vf + 4, stg + OVOF + aswz(32 + lane, n));
#pragma unroll
            for (int ks = 0; ks < 4; ks++)
                mma16816h(o[n], pa[ks], vf + 2 * ks);
        }

        __syncthreads();
        if (kb + 2 < nkb) { issueKV(kb + 2, kb & 1); cp_commit(); }
    }

    // ---- epilogue: normalize, emit bf16 hi/lo into g_Oh/g_Ol [B*T, C] ----
    float inv0 = 1.f / l_i0, inv1 = 1.f / l_i1;
    int t0 = qrow0 + m0 + gid;
    size_t rb0 = ((size_t)(b * TT + t0)) * CC + h * DD;
    size_t rb1 = rb0 + (size_t)8 * CC;
#pragma unroll
    for (int n = 0; n < 8; n++) {
        u32 H, L;
        int coff = 8 * n + 2 * tig;
        split2u(o[n][0] * inv0, o[n][1] * inv0, H, L);
        *(u32*)&g_Oh[rb0 + coff] = H;
        *(u32*)&g_Ol[rb0 + coff] = L;
        split2u(o[n][2] * inv1, o[n][3] * inv1, H, L);
        *(u32*)&g_Oh[rb1 + coff] = H;
        *(u32*)&g_Ol[rb1 + coff] = L;
    }
}

// ---------------------------------------------------------------------------
extern "C" void kernel_launch(void* const* d_in, const int* in_sizes, int n_in,
                              void* d_out, int out_size)
{
    const float* x     = (const float*)d_in[0];
    // d_in[1] = mask (bool) — causal, applied analytically
    const float* w_qkv = (const float*)d_in[2];
    const float* w_out = (const float*)d_in[3];
    float* out = (float*)d_out;

    // 0) split inputs into bf16 hi/lo
    cvt_split<<<(MTOT * CC / 4) / 256, 256>>>((const float4*)x, 0);
    cvt_split<<<(NQKV * CC / 4) / 256, 256>>>((const float4*)w_qkv, 1);
    cvt_split<<<(CC * CC / 4) / 256, 256>>>((const float4*)w_out, 2);

    // 1) QKV projection via mma.sync -> fp16 Q(scaled)/K/V
    cudaFuncSetAttribute(mma_gemm<0>, cudaFuncAttributeMaxDynamicSharedMemorySize,
                         GSMEM);
    mma_gemm<0><<<dim3(NQKV / 256, MTOT / 128), 256, GSMEM>>>(nullptr);

    // 2) causal flash attention (fp16 mma.sync) -> g_Oh/g_Ol
    cudaFuncSetAttribute(flash_attn_fp16,
                         cudaFuncAttributeMaxDynamicSharedMemorySize, ASMEM);
    flash_attn_fp16<<<dim3(TT / QTILE, HH, BB), 256, ASMEM>>>();

    // 3) output projection via mma.sync -> d_out
    cudaFuncSetAttribute(mma_gemm<1>, cudaFuncAttributeMaxDynamicSharedMemorySize,
                         GSMEM);
    mma_gemm<1><<<dim3(CC / 256, MTOT / 128), 256, GSMEM>>>(out);
}

// round 13
// speedup vs baseline: 5.6016x; 1.6374x over previous
#include <cuda_runtime.h>
#include <cuda_bf16.h>
#include <cuda_fp16.h>
#include <cstdint>
#include <math.h>

// Problem constants
#define BB   4
#define TT   2048
#define CC   1024
#define HH   16
#define DD   64
#define MTOT (BB*TT)          // 8192
#define NQKV (3*CC)           // 3072

typedef unsigned long long u64;
typedef unsigned int u32;

// ---------------------------------------------------------------------------
// Scratch in device globals (no allocations allowed) — all fp16 now
// ---------------------------------------------------------------------------
__device__ __half g_xf[(size_t)MTOT*CC];
__device__ __half g_wqf[(size_t)NQKV*CC];
__device__ __half g_wof[(size_t)CC*CC];
__device__ __half g_Of[(size_t)MTOT*CC];
__device__ __half g_Qf[(size_t)BB*HH*TT*DD];
__device__ __half g_Kf[(size_t)BB*HH*TT*DD];
__device__ __half g_Vf[(size_t)BB*HH*TT*DD];

// ---------------------------------------------------------------------------
// PTX helpers (plain sm_103 target)
// ---------------------------------------------------------------------------
__device__ __forceinline__ void cp_async16(u32 saddr, const void* gaddr) {
    asm volatile("cp.async.cg.shared.global [%0], [%1], 16;"
                 :: "r"(saddr), "l"(gaddr));
}
__device__ __forceinline__ void cp_commit() {
    asm volatile("cp.async.commit_group;");
}
template<int N>
__device__ __forceinline__ void cp_wait() {
    asm volatile("cp.async.wait_group %0;" :: "n"(N));
}
__device__ __forceinline__ void ldsm_x4(u32* r, u32 addr) {
    asm volatile("ldmatrix.sync.aligned.m8n8.x4.shared.b16 {%0,%1,%2,%3}, [%4];"
                 : "=r"(r[0]), "=r"(r[1]), "=r"(r[2]), "=r"(r[3]) : "r"(addr));
}
__device__ __forceinline__ void ldsm_x4_t(u32* r, u32 addr) {
    asm volatile("ldmatrix.sync.aligned.m8n8.x4.trans.shared.b16 {%0,%1,%2,%3}, [%4];"
                 : "=r"(r[0]), "=r"(r[1]), "=r"(r[2]), "=r"(r[3]) : "r"(addr));
}
__device__ __forceinline__ void mma16816h(float* d, const u32* a, const u32* b) {
    asm volatile(
        "mma.sync.aligned.m16n8k16.row.col.f32.f16.f16.f32 "
        "{%0,%1,%2,%3}, {%4,%5,%6,%7}, {%8,%9}, {%0,%1,%2,%3};"
        : "+f"(d[0]), "+f"(d[1]), "+f"(d[2]), "+f"(d[3])
        : "r"(a[0]), "r"(a[1]), "r"(a[2]), "r"(a[3]), "r"(b[0]), "r"(b[1]));
}
__device__ __forceinline__ u32 packh2(float x, float y) {
    __half2 h = __floats2half2_rn(x, y);   // low=x, high=y
    return *(u32*)&h;
}

// ---------------------------------------------------------------------------
// fp32 -> fp16 conversion (x, w_qkv, w_out)
// ---------------------------------------------------------------------------
__global__ __launch_bounds__(256)
void cvt_half(const float4* __restrict__ src, int which)
{
    size_t i = (size_t)blockIdx.x * 256 + threadIdx.x;
    float4 v = src[i];
    uint2 H;
    H.x = packh2(v.x, v.y);
    H.y = packh2(v.z, v.w);
    uint2* hp;
    if (which == 0)      hp = (uint2*)g_xf;
    else if (which == 1) hp = (uint2*)g_wqf;
    else                 hp = (uint2*)g_wof;
    hp[i] = H;
}

// ---------------------------------------------------------------------------
// mma.sync GEMM (NT), fp16 single: C[m,n] = sum_k A[m,k]*B[n,k], fp32 acc.
// CTA tile 128x128, 8 warps as 2(wm) x 4(wn) -> 64x32 per warp.
// K-tile 32, cp.async double buffer. Stage: A 8KB @0, B 8KB @8192 = 16KB.
// EPI==0: A=g_xf, B=g_wqf -> g_Qf(*0.125)/g_Kf/g_Vf fp16 [B,H,T,D]
// EPI==1: A=g_Of, B=g_wof -> fp32 row-major Cout
// ---------------------------------------------------------------------------
#define STAGE_BYTES 16384
#define GSMEM (2 * STAGE_BYTES)

__device__ __forceinline__ u32 swz_off(int row, int chunk) {
    int key = (row ^ (row >> 2)) & 3;
    return (u32)(row * 64 + ((chunk ^ key) << 4));
}

template<int EPI>
__global__ __launch_bounds__(256)
void mma_gemm(float* __restrict__ Cout)
{
    extern __shared__ char smem[];
    const u32 sb = (u32)__cvta_generic_to_shared(smem);
    const int tid = threadIdx.x;
    const int wid = tid >> 5, lane = tid & 31;
    const int bn = blockIdx.x, bm = blockIdx.y;

    const __half* A  = EPI ? g_Of  : g_xf;
    const __half* Bw = EPI ? g_wof : g_wqf;

    const int arow = bm * 128, brow = bn * 128;
    const int lrow = tid >> 2, lchunk = tid & 3;

    auto issue = [&](int kb, int st) {
        const int kcol = kb * 32 + lchunk * 8;
        u32 base = sb + st * STAGE_BYTES;
#pragma unroll
        for (int i = 0; i < 2; i++) {
            int row = lrow + i * 64;
            u32 so = swz_off(row, lchunk);
            cp_async16(base + so,        A  + (size_t)(arow + row) * CC + kcol);
            cp_async16(base + 8192 + so, Bw + (size_t)(brow + row) * CC + kcol);
        }
        cp_commit();
    };

    const int wm = wid & 1, wn = wid >> 1;

    // ldmatrix base addresses (stage 0)
    u32 aaddr0[4], baddr0[4];
    {
        int mat = lane >> 3, sr = lane & 7;
        int arow_l = wm * 64 + sr + (mat & 1) * 8;
        int achunk = mat >> 1;           // k-chunk 0/1 (ks=0); ks=1 via ^0x20
#pragma unroll
        for (int mt = 0; mt < 4; mt++)
            aaddr0[mt] = sb + swz_off(arow_l + mt * 16, achunk);
        // B x4: 4 matrices = k-chunks 0..3 (whole k32) for one n8 tile
        int brow_l = wn * 32 + (lane & 7);
        int bchunk = lane >> 3;          // 0..3
#pragma unroll
        for (int nt = 0; nt < 4; nt++)
            baddr0[nt] = sb + 8192 + swz_off(brow_l + nt * 8, bchunk);
    }

    float acc[4][4][4];
#pragma unroll
    for (int mt = 0; mt < 4; mt++)
#pragma unroll
        for (int nt = 0; nt < 4; nt++)
#pragma unroll
            for (int e = 0; e < 4; e++) acc[mt][nt][e] = 0.f;

    const int nk = CC / 32;
    issue(0, 0);

    for (int kb = 0; kb < nk; kb++) {
        const int st = kb & 1;
        if (kb + 1 < nk) { issue(kb + 1, st ^ 1); cp_wait<1>(); }
        else             { cp_wait<0>(); }
        __syncthreads();

        const u32 soff = (u32)(st * STAGE_BYTES);
        u32 a4[2][4][4], b4[4][4];
#pragma unroll
        for (int ks = 0; ks < 2; ks++)
#pragma unroll
            for (int mt = 0; mt < 4; mt++)
                ldsm_x4(a4[ks][mt], (aaddr0[mt] + soff) ^ (u32)(ks << 5));
#pragma unroll
        for (int nt = 0; nt < 4; nt++)
            ldsm_x4(b4[nt], baddr0[nt] + soff);
#pragma unroll
        for (int ks = 0; ks < 2; ks++)
#pragma unroll
            for (int mt = 0; mt < 4; mt++)
#pragma unroll
                for (int nt = 0; nt < 4; nt++)
                    mma16816h(acc[mt][nt], a4[ks][mt], b4[nt] + 2 * ks);
        __syncthreads();
    }

    const int gid = lane >> 2, tig = lane & 3;
#pragma unroll
    for (int mt = 0; mt < 4; mt++) {
#pragma unroll
        for (int half = 0; half < 2; half++) {
            int m = bm * 128 + wm * 64 + mt * 16 + gid + half * 8;
#pragma unroll
            for (int nt = 0; nt < 4; nt++) {
                float c0 = acc[mt][nt][half * 2 + 0];
                float c1 = acc[mt][nt][half * 2 + 1];
                int n = bn * 128 + wn * 32 + nt * 8 + 2 * tig;
                if (EPI == 0) {
                    int sec = n >> 10, cn = n & 1023;
                    int h = cn >> 6, d = cn & 63;
                    int b = m >> 11, t = m & 2047;
                    size_t idx = (((size_t)(b * HH + h)) * TT + t) * DD + d;
                    __half* dst;
                    if (sec == 0) { c0 *= 0.125f; c1 *= 0.125f; dst = g_Qf; }
                    else if (sec == 1) dst = g_Kf;
                    else               dst = g_Vf;
                    *(u32*)&dst[idx] = packh2(c0, c1);
                } else {
                    *(float2*)&Cout[(size_t)m * CC + n] = make_float2(c0, c1);
                }
            }
        }
    }
}

// ---------------------------------------------------------------------------
// Flash attention (causal) via single-pass fp16 mma.sync.
// CTA: 128-query tile, 8 warps x 16 rows; key blocks of 64, cp.async
// double-buffered K/V. Warp-local online softmax. O in fp32.
// smem: Q @0 (16KB), stage s @16K+16K*s: K +0, V +8K. Total 48KB.
// ---------------------------------------------------------------------------
#define QTILE 128
#define KTILE 64
#define ASTG(s) (16384 + (s) * 16384)
#define OKOF 0
#define OVOF 8192
#define ASMEM 49152

__device__ __forceinline__ u32 aswz(int row, int chunk) {
    return (u32)(row * 128 + ((chunk ^ (row & 7)) << 4));
}

__global__ __launch_bounds__(256)
void flash_attn_fp16()
{
    extern __shared__ char smem[];
    const u32 sb = (u32)__cvta_generic_to_shared(smem);
    const int tid = threadIdx.x;
    const int wid = tid >> 5, lane = tid & 31;
    const int b = blockIdx.z, h = blockIdx.y;
    const int qb = gridDim.x - 1 - blockIdx.x;   // heavy tiles first
    const size_t hbase = (size_t)(b * HH + h) * TT * DD;
    const int qrow0 = qb * QTILE;
    const int nkb = 2 * qb + 2;

    // ---- Q tile (fp16): 1024 chunks, 4 per thread ----
#pragma unroll
    for (int i = 0; i < 4; i++) {
        int id = tid + i * 256;
        int row = id >> 3, ch = id & 7;
        cp_async16(sb + aswz(row, ch),
                   g_Qf + hbase + (size_t)(qrow0 + row) * DD + ch * 8);
    }
    // ---- K/V stage issue: 1024 chunks, 4 per thread ----
    auto issueKV = [&](int kb, int st) {
        u32 base = sb + ASTG(st);
        int t0 = kb * KTILE;
#pragma unroll
        for (int i = 0; i < 4; i++) {
            int id = tid + i * 256;
            int tens = id >> 9;              // 0 K, 1 V
            int rem = id & 511;
            int row = rem >> 3, ch = rem & 7;
            const __half* src = tens ? g_Vf : g_Kf;
            u32 off = tens ? OVOF : OKOF;
            cp_async16(base + off + aswz(row, ch),
                       src + hbase + (size_t)(t0 + row) * DD + ch * 8);
        }
    };

    issueKV(0, 0); cp_commit();           // group 0: Q + stage0
    issueKV(1, 1); cp_commit();           // group 1: stage1

    const int m0 = wid * 16;
    const int gid = lane >> 2, tig = lane & 3;
    const int r0g = qrow0 + m0 + gid;
    const int r1g = r0g + 8;

    u32 qf[4][4];
    float o[8][4];
    float m_i0 = -INFINITY, m_i1 = -INFINITY, l_i0 = 0.f, l_i1 = 0.f;
#pragma unroll
    for (int n = 0; n < 8; n++)
#pragma unroll
        for (int e = 0; e < 4; e++) o[n][e] = 0.f;

    for (int kb = 0; kb < nkb; kb++) {
        if (kb + 1 < nkb) cp_wait<1>(); else cp_wait<0>();
        __syncthreads();

        if (kb == 0) {   // load Q fragments once
            int qrow = m0 + (lane & 15);
            int csel = lane >> 4;
#pragma unroll
            for (int ks = 0; ks < 4; ks++)
                ldsm_x4(qf[ks], sb + aswz(qrow, 2 * ks + csel));
        }

        const u32 stg = sb + ASTG(kb & 1);

        // ---- S = Q K^T (16 x 64 per warp) ----
        float s[8][4];
#pragma unroll
        for (int j = 0; j < 8; j++) {
            s[j][0] = s[j][1] = s[j][2] = s[j][3] = 0.f;
            u32 kf[8];
            int krow = 8 * j + (lane & 7);
            int kc = lane >> 3;              // 0..3
            ldsm_x4(kf,     stg + OKOF + aswz(krow, kc));
            ldsm_x4(kf + 4, stg + OKOF + aswz(krow, 4 + kc));
#pragma unroll
            for (int ks = 0; ks < 4; ks++)
                mma16816h(s[j], qf[ks], kf + 2 * ks);
        }

        // ---- causal mask (diagonal-region blocks only) ----
        if (kb >= 2 * qb) {
#pragma unroll
            for (int j = 0; j < 8; j++) {
                int c = kb * KTILE + 8 * j + 2 * tig;
                if (c     > r0g) s[j][0] = -INFINITY;
                if (c + 1 > r0g) s[j][1] = -INFINITY;
                if (c     > r1g) s[j][2] = -INFINITY;
                if (c + 1 > r1g) s[j][3] = -INFINITY;
            }
        }

        // ---- online softmax (rows r0g, r1g; reduce over 4 quad lanes) ----
        float mx0 = -INFINITY, mx1 = -INFINITY;
#pragma unroll
        for (int j = 0; j < 8; j++) {
            mx0 = fmaxf(mx0, fmaxf(s[j][0], s[j][1]));
            mx1 = fmaxf(mx1, fmaxf(s[j][2], s[j][3]));
        }
        mx0 = fmaxf(mx0, __shfl_xor_sync(0xffffffffu, mx0, 1));
        mx0 = fmaxf(mx0, __shfl_xor_sync(0xffffffffu, mx0, 2));
        mx1 = fmaxf(mx1, __shfl_xor_sync(0xffffffffu, mx1, 1));
        mx1 = fmaxf(mx1, __shfl_xor_sync(0xffffffffu, mx1, 2));
        float mn0 = fmaxf(m_i0, mx0), mn1 = fmaxf(m_i1, mx1);
        float al0 = __expf(m_i0 - mn0), al1 = __expf(m_i1 - mn1);
        float sum0 = 0.f, sum1 = 0.f;
#pragma unroll
        for (int j = 0; j < 8; j++) {
            s[j][0] = __expf(s[j][0] - mn0);
            s[j][1] = __expf(s[j][1] - mn0);
            s[j][2] = __expf(s[j][2] - mn1);
            s[j][3] = __expf(s[j][3] - mn1);
            sum0 += s[j][0] + s[j][1];
            sum1 += s[j][2] + s[j][3];
        }
        sum0 += __shfl_xor_sync(0xffffffffu, sum0, 1);
        sum0 += __shfl_xor_sync(0xffffffffu, sum0, 2);
        sum1 += __shfl_xor_sync(0xffffffffu, sum1, 1);
        sum1 += __shfl_xor_sync(0xffffffffu, sum1, 2);
        l_i0 = al0 * l_i0 + sum0;  m_i0 = mn0;
        l_i1 = al1 * l_i1 + sum1;  m_i1 = mn1;
#pragma unroll
        for (int n = 0; n < 8; n++) {
            o[n][0] *= al0; o[n][1] *= al0;
            o[n][2] *= al1; o[n][3] *= al1;
        }

        // ---- P -> fp16 A-fragments (register repack) ----
        u32 pa[4][4];
#pragma unroll
        for (int ks = 0; ks < 4; ks++) {
            pa[ks][0] = packh2(s[2*ks][0],   s[2*ks][1]);
            pa[ks][1] = packh2(s[2*ks][2],   s[2*ks][3]);
            pa[ks][2] = packh2(s[2*ks+1][0], s[2*ks+1][1]);
            pa[ks][3] = packh2(s[2*ks+1][2], s[2*ks+1][3]);
        }

        // ---- O += P V  (V via ldmatrix.trans) ----
#pragma unroll
        for (int n = 0; n < 8; n++) {
            u32 vf[8];
            ldsm_x4_t(vf,     stg + OVOF + aswz(lane, n));
            ldsm_x4_t(vf + 4, stg + OVOF + aswz(32 + lane, n));
#pragma unroll
            for (int ks = 0; ks < 4; ks++)
                mma16816h(o[n], pa[ks], vf + 2 * ks);
        }

        __syncthreads();
        if (kb + 2 < nkb) { issueKV(kb + 2, kb & 1); cp_commit(); }
    }

    // ---- epilogue: normalize, emit fp16 into g_Of [B*T, C] ----
    float inv0 = 1.f / l_i0, inv1 = 1.f / l_i1;
    int t0 = qrow0 + m0 + gid;
    size_t rb0 = ((size_t)(b * TT + t0)) * CC + h * DD;
    size_t rb1 = rb0 + (size_t)8 * CC;
#pragma unroll
    for (int n = 0; n < 8; n++) {
        int coff = 8 * n + 2 * tig;
        *(u32*)&g_Of[rb0 + coff] = packh2(o[n][0] * inv0, o[n][1] * inv0);
        *(u32*)&g_Of[rb1 + coff] = packh2(o[n][2] * inv1, o[n][3] * inv1);
    }
}

// ---------------------------------------------------------------------------
extern "C" void kernel_launch(void* const* d_in, const int* in_sizes, int n_in,
                              void* d_out, int out_size)
{
    const float* x     = (const float*)d_in[0];
    // d_in[1] = mask (bool) — causal, applied analytically
    const float* w_qkv = (const float*)d_in[2];
    const float* w_out = (const float*)d_in[3];
    float* out = (float*)d_out;

    // 0) convert inputs to fp16
    cvt_half<<<(MTOT * CC / 4) / 256, 256>>>((const float4*)x, 0);
    cvt_half<<<(NQKV * CC / 4) / 256, 256>>>((const float4*)w_qkv, 1);
    cvt_half<<<(CC * CC / 4) / 256, 256>>>((const float4*)w_out, 2);

    // 1) QKV projection via fp16 mma.sync -> fp16 Q(scaled)/K/V
    cudaFuncSetAttribute(mma_gemm<0>, cudaFuncAttributeMaxDynamicSharedMemorySize,
                         GSMEM);
    mma_gemm<0><<<dim3(NQKV / 128, MTOT / 128), 256, GSMEM>>>(nullptr);

    // 2) causal flash attention (fp16 mma.sync) -> g_Of
    cudaFuncSetAttribute(flash_attn_fp16,
                         cudaFuncAttributeMaxDynamicSharedMemorySize, ASMEM);
    flash_attn_fp16<<<dim3(TT / QTILE, HH, BB), 256, ASMEM>>>();

    // 3) output projection via fp16 mma.sync -> d_out
    cudaFuncSetAttribute(mma_gemm<1>, cudaFuncAttributeMaxDynamicSharedMemorySize,
                         GSMEM);
    mma_gemm<1><<<dim3(CC / 128, MTOT / 128), 256, GSMEM>>>(out);
}

// round 16
// speedup vs baseline: 7.0788x; 1.2637x over previous
#include <cuda_runtime.h>
#include <cuda_bf16.h>
#include <cuda_fp16.h>
#include <cstdint>
#include <math.h>

// Problem constants
#define BB   4
#define TT   2048
#define CC   1024
#define HH   16
#define DD   64
#define MTOT (BB*TT)          // 8192
#define NQKV (3*CC)           // 3072

typedef unsigned long long u64;
typedef unsigned int u32;

// ---------------------------------------------------------------------------
// Scratch in device globals (no allocations allowed) — all fp16
// ---------------------------------------------------------------------------
__device__ __half g_xf[(size_t)MTOT*CC];
__device__ __half g_wqf[(size_t)NQKV*CC];
__device__ __half g_wof[(size_t)CC*CC];
__device__ __half g_Of[(size_t)MTOT*CC];
__device__ __half g_Qf[(size_t)BB*HH*TT*DD];
__device__ __half g_Kf[(size_t)BB*HH*TT*DD];
__device__ __half g_Vf[(size_t)BB*HH*TT*DD];

// ---------------------------------------------------------------------------
// PTX helpers (plain sm_103 target)
// ---------------------------------------------------------------------------
__device__ __forceinline__ void cp_async16(u32 saddr, const void* gaddr) {
    asm volatile("cp.async.cg.shared.global [%0], [%1], 16;"
                 :: "r"(saddr), "l"(gaddr));
}
__device__ __forceinline__ void cp_commit() {
    asm volatile("cp.async.commit_group;");
}
template<int N>
__device__ __forceinline__ void cp_wait() {
    asm volatile("cp.async.wait_group %0;" :: "n"(N));
}
__device__ __forceinline__ void ldsm_x4(u32* r, u32 addr) {
    asm volatile("ldmatrix.sync.aligned.m8n8.x4.shared.b16 {%0,%1,%2,%3}, [%4];"
                 : "=r"(r[0]), "=r"(r[1]), "=r"(r[2]), "=r"(r[3]) : "r"(addr));
}
__device__ __forceinline__ void ldsm_x4_t(u32* r, u32 addr) {
    asm volatile("ldmatrix.sync.aligned.m8n8.x4.trans.shared.b16 {%0,%1,%2,%3}, [%4];"
                 : "=r"(r[0]), "=r"(r[1]), "=r"(r[2]), "=r"(r[3]) : "r"(addr));
}
__device__ __forceinline__ void mma16816h(float* d, const u32* a, const u32* b) {
    asm volatile(
        "mma.sync.aligned.m16n8k16.row.col.f32.f16.f16.f32 "
        "{%0,%1,%2,%3}, {%4,%5,%6,%7}, {%8,%9}, {%0,%1,%2,%3};"
        : "+f"(d[0]), "+f"(d[1]), "+f"(d[2]), "+f"(d[3])
        : "r"(a[0]), "r"(a[1]), "r"(a[2]), "r"(a[3]), "r"(b[0]), "r"(b[1]));
}
__device__ __forceinline__ u32 packh2(float x, float y) {
    __half2 h = __floats2half2_rn(x, y);   // low=x, high=y
    return *(u32*)&h;
}

// ---------------------------------------------------------------------------
// fp32 -> fp16 conversion, single launch for x, w_qkv, w_out
// ---------------------------------------------------------------------------
#define N0 ((size_t)MTOT*CC/4)
#define N1 ((size_t)NQKV*CC/4)
#define N2 ((size_t)CC*CC/4)

__global__ __launch_bounds__(256)
void cvt_all(const float4* __restrict__ x, const float4* __restrict__ wq,
             const float4* __restrict__ wo)
{
    size_t i = (size_t)blockIdx.x * 256 + threadIdx.x;
    const float4* src;
    uint2* dst;
    size_t j;
    if (i < N0)            { src = x;  dst = (uint2*)g_xf;  j = i; }
    else if (i < N0 + N1)  { src = wq; dst = (uint2*)g_wqf; j = i - N0; }
    else                   { src = wo; dst = (uint2*)g_wof; j = i - N0 - N1; }
    float4 v = src[j];
    uint2 H;
    H.x = packh2(v.x, v.y);
    H.y = packh2(v.z, v.w);
    dst[j] = H;
}

// ---------------------------------------------------------------------------
// mma.sync GEMM (NT), fp16: C[m,n] = sum_k A[m,k]*B[n,k], fp32 acc.
// CTA tile 128x128, 8 warps as 2(wm) x 4(wn) -> 64x32 per warp.
// K-tile 32, 4-stage cp.async ring, ONE __syncthreads per k-tile.
// EPI==0: A=g_xf, B=g_wqf -> g_Qf(*0.125)/g_Kf/g_Vf fp16 [B,H,T,D]
// EPI==1: A=g_Of, B=g_wof -> fp32 row-major Cout
// ---------------------------------------------------------------------------
#define STAGE_BYTES 16384
#define NSTAGE 4
#define GSMEM (NSTAGE * STAGE_BYTES)

__device__ __forceinline__ u32 swz_off(int row, int chunk) {
    int key = (row ^ (row >> 2)) & 3;
    return (u32)(row * 64 + ((chunk ^ key) << 4));
}

template<int EPI>
__global__ __launch_bounds__(256, 2)
void mma_gemm(float* __restrict__ Cout)
{
    extern __shared__ char smem[];
    const u32 sb = (u32)__cvta_generic_to_shared(smem);
    const int tid = threadIdx.x;
    const int wid = tid >> 5, lane = tid & 31;
    const int bn = blockIdx.x, bm = blockIdx.y;

    const __half* A  = EPI ? g_Of  : g_xf;
    const __half* Bw = EPI ? g_wof : g_wqf;

    const int arow = bm * 128, brow = bn * 128;
    const int lrow = tid >> 2, lchunk = tid & 3;

    auto issue = [&](int kb, int st) {
        const int kcol = kb * 32 + lchunk * 8;
        u32 base = sb + st * STAGE_BYTES;
#pragma unroll
        for (int i = 0; i < 2; i++) {
            int row = lrow + i * 64;
            u32 so = swz_off(row, lchunk);
            cp_async16(base + so,        A  + (size_t)(arow + row) * CC + kcol);
            cp_async16(base + 8192 + so, Bw + (size_t)(brow + row) * CC + kcol);
        }
        cp_commit();
    };

    const int wm = wid & 1, wn = wid >> 1;

    // ldmatrix base addresses (stage 0)
    u32 aaddr0[4], baddr0[4];
    {
        int mat = lane >> 3, sr = lane & 7;
        int arow_l = wm * 64 + sr + (mat & 1) * 8;
        int achunk = mat >> 1;           // k-chunk 0/1 (ks=0); ks=1 via ^0x20
#pragma unroll
        for (int mt = 0; mt < 4; mt++)
            aaddr0[mt] = sb + swz_off(arow_l + mt * 16, achunk);
        // B x4: 4 matrices = k-chunks 0..3 (whole k32) for one n8 tile
        int brow_l = wn * 32 + (lane & 7);
        int bchunk = lane >> 3;          // 0..3
#pragma unroll
        for (int nt = 0; nt < 4; nt++)
            baddr0[nt] = sb + 8192 + swz_off(brow_l + nt * 8, bchunk);
    }

    float acc[4][4][4];
#pragma unroll
    for (int mt = 0; mt < 4; mt++)
#pragma unroll
        for (int nt = 0; nt < 4; nt++)
#pragma unroll
            for (int e = 0; e < 4; e++) acc[mt][nt][e] = 0.f;

    const int nk = CC / 32;   // 32

    issue(0, 0); issue(1, 1); issue(2, 2);

    for (int kb = 0; kb < nk; kb++) {
        // entering iter kb: issued groups 0..kb+2
        if (kb < nk - 2)       cp_wait<2>();
        else if (kb == nk - 2) cp_wait<1>();
        else                   cp_wait<0>();
        __syncthreads();

        const u32 soff = (u32)((kb & 3) * STAGE_BYTES);
        u32 a4[2][4][4], b4[4][4];
#pragma unroll
        for (int ks = 0; ks < 2; ks++)
#pragma unroll
            for (int mt = 0; mt < 4; mt++)
                ldsm_x4(a4[ks][mt], (aaddr0[mt] + soff) ^ (u32)(ks << 5));
#pragma unroll
        for (int nt = 0; nt < 4; nt++)
            ldsm_x4(b4[nt], baddr0[nt] + soff);
#pragma unroll
        for (int ks = 0; ks < 2; ks++)
#pragma unroll
            for (int mt = 0; mt < 4; mt++)
#pragma unroll
                for (int nt = 0; nt < 4; nt++)
                    mma16816h(acc[mt][nt], a4[ks][mt], b4[nt] + 2 * ks);

        // Issue next group AFTER compute: writes stage (kb+3)&3 == (kb-1)&3,
        // whose readers (iter kb-1) all passed this iteration's barrier.
        if (kb + 3 < nk) issue(kb + 3, (kb + 3) & 3);
    }

    const int gid = lane >> 2, tig = lane & 3;
#pragma unroll
    for (int mt = 0; mt < 4; mt++) {
#pragma unroll
        for (int half = 0; half < 2; half++) {
            int m = bm * 128 + wm * 64 + mt * 16 + gid + half * 8;
#pragma unroll
            for (int nt = 0; nt < 4; nt++) {
                float c0 = acc[mt][nt][half * 2 + 0];
                float c1 = acc[mt][nt][half * 2 + 1];
                int n = bn * 128 + wn * 32 + nt * 8 + 2 * tig;
                if (EPI == 0) {
                    int sec = n >> 10, cn = n & 1023;
                    int h = cn >> 6, d = cn & 63;
                    int b = m >> 11, t = m & 2047;
                    size_t idx = (((size_t)(b * HH + h)) * TT + t) * DD + d;
                    __half* dst;
                    if (sec == 0) { c0 *= 0.125f; c1 *= 0.125f; dst = g_Qf; }
                    else if (sec == 1) dst = g_Kf;
                    else               dst = g_Vf;
                    *(u32*)&dst[idx] = packh2(c0, c1);
                } else {
                    *(float2*)&Cout[(size_t)m * CC + n] = make_float2(c0, c1);
                }
            }
        }
    }
}

// ---------------------------------------------------------------------------
// Flash attention (causal) via single-pass fp16 mma.sync.
// CTA: 128-query tile, 8 warps x 16 rows; key blocks of 64, cp.async
// double-buffered K/V. Warp-local online softmax. O in fp32.
// smem: Q @0 (16KB), stage s @16K+16K*s: K +0, V +8K. Total 48KB.
// ---------------------------------------------------------------------------
#define QTILE 128
#define KTILE 64
#define ASTG(s) (16384 + (s) * 16384)
#define OKOF 0
#define OVOF 8192
#define ASMEM 49152

__device__ __forceinline__ u32 aswz(int row, int chunk) {
    return (u32)(row * 128 + ((chunk ^ (row & 7)) << 4));
}

__global__ __launch_bounds__(256, 2)
void flash_attn_fp16()
{
    extern __shared__ char smem[];
    const u32 sb = (u32)__cvta_generic_to_shared(smem);
    const int tid = threadIdx.x;
    const int wid = tid >> 5, lane = tid & 31;
    const int b = blockIdx.z, h = blockIdx.y;
    const int qb = gridDim.x - 1 - blockIdx.x;   // heavy tiles first
    const size_t hbase = (size_t)(b * HH + h) * TT * DD;
    const int qrow0 = qb * QTILE;
    const int nkb = 2 * qb + 2;

    // ---- Q tile (fp16): 1024 chunks, 4 per thread ----
#pragma unroll
    for (int i = 0; i < 4; i++) {
        int id = tid + i * 256;
        int row = id >> 3, ch = id & 7;
        cp_async16(sb + aswz(row, ch),
                   g_Qf + hbase + (size_t)(qrow0 + row) * DD + ch * 8);
    }
    // ---- K/V stage issue: 1024 chunks, 4 per thread ----
    auto issueKV = [&](int kb, int st) {
        u32 base = sb + ASTG(st);
        int t0 = kb * KTILE;
#pragma unroll
        for (int i = 0; i < 4; i++) {
            int id = tid + i * 256;
            int tens = id >> 9;              // 0 K, 1 V
            int rem = id & 511;
            int row = rem >> 3, ch = rem & 7;
            const __half* src = tens ? g_Vf : g_Kf;
            u32 off = tens ? OVOF : OKOF;
            cp_async16(base + off + aswz(row, ch),
                       src + hbase + (size_t)(t0 + row) * DD + ch * 8);
        }
    };

    issueKV(0, 0); cp_commit();           // group 0: Q + stage0
    issueKV(1, 1); cp_commit();           // group 1: stage1

    const int m0 = wid * 16;
    const int gid = lane >> 2, tig = lane & 3;
    const int r0g = qrow0 + m0 + gid;
    const int r1g = r0g + 8;

    u32 qf[4][4];
    float o[8][4];
    float m_i0 = -INFINITY, m_i1 = -INFINITY, l_i0 = 0.f, l_i1 = 0.f;
#pragma unroll
    for (int n = 0; n < 8; n++)
#pragma unroll
        for (int e = 0; e < 4; e++) o[n][e] = 0.f;

    for (int kb = 0; kb < nkb; kb++) {
        if (kb + 1 < nkb) cp_wait<1>(); else cp_wait<0>();
        __syncthreads();

        if (kb == 0) {   // load Q fragments once
            int qrow = m0 + (lane & 15);
            int csel = lane >> 4;
#pragma unroll
            for (int ks = 0; ks < 4; ks++)
                ldsm_x4(qf[ks], sb + aswz(qrow, 2 * ks + csel));
        }

        const u32 stg = sb + ASTG(kb & 1);

        // ---- S = Q K^T (16 x 64 per warp) ----
        float s[8][4];
#pragma unroll
        for (int j = 0; j < 8; j++) {
            s[j][0] = s[j][1] = s[j][2] = s[j][3] = 0.f;
            u32 kf[8];
            int krow = 8 * j + (lane & 7);
            int kc = lane >> 3;              // 0..3
            ldsm_x4(kf,     stg + OKOF + aswz(krow, kc));
            ldsm_x4(kf + 4, stg + OKOF + aswz(krow, 4 + kc));
#pragma unroll
            for (int ks = 0; ks < 4; ks++)
                mma16816h(s[j], qf[ks], kf + 2 * ks);
        }

        // ---- causal mask (diagonal-region blocks only) ----
        if (kb >= 2 * qb) {
#pragma unroll
            for (int j = 0; j < 8; j++) {
                int c = kb * KTILE + 8 * j + 2 * tig;
                if (c     > r0g) s[j][0] = -INFINITY;
                if (c + 1 > r0g) s[j][1] = -INFINITY;
                if (c     > r1g) s[j][2] = -INFINITY;
                if (c + 1 > r1g) s[j][3] = -INFINITY;
            }
        }

        // ---- online softmax (rows r0g, r1g; reduce over 4 quad lanes) ----
        float mx0 = -INFINITY, mx1 = -INFINITY;
#pragma unroll
        for (int j = 0; j < 8; j++) {
            mx0 = fmaxf(mx0, fmaxf(s[j][0], s[j][1]));
            mx1 = fmaxf(mx1, fmaxf(s[j][2], s[j][3]));
        }
        mx0 = fmaxf(mx0, __shfl_xor_sync(0xffffffffu, mx0, 1));
        mx0 = fmaxf(mx0, __shfl_xor_sync(0xffffffffu, mx0, 2));
        mx1 = fmaxf(mx1, __shfl_xor_sync(0xffffffffu, mx1, 1));
        mx1 = fmaxf(mx1, __shfl_xor_sync(0xffffffffu, mx1, 2));
        float mn0 = fmaxf(m_i0, mx0), mn1 = fmaxf(m_i1, mx1);
        float al0 = __expf(m_i0 - mn0), al1 = __expf(m_i1 - mn1);
        float sum0 = 0.f, sum1 = 0.f;
#pragma unroll
        for (int j = 0; j < 8; j++) {
            s[j][0] = __expf(s[j][0] - mn0);
            s[j][1] = __expf(s[j][1] - mn0);
            s[j][2] = __expf(s[j][2] - mn1);
            s[j][3] = __expf(s[j][3] - mn1);
            sum0 += s[j][0] + s[j][1];
            sum1 += s[j][2] + s[j][3];
        }
        sum0 += __shfl_xor_sync(0xffffffffu, sum0, 1);
        sum0 += __shfl_xor_sync(0xffffffffu, sum0, 2);
        sum1 += __shfl_xor_sync(0xffffffffu, sum1, 1);
        sum1 += __shfl_xor_sync(0xffffffffu, sum1, 2);
        l_i0 = al0 * l_i0 + sum0;  m_i0 = mn0;
        l_i1 = al1 * l_i1 + sum1;  m_i1 = mn1;
#pragma unroll
        for (int n = 0; n < 8; n++) {
            o[n][0] *= al0; o[n][1] *= al0;
            o[n][2] *= al1; o[n][3] *= al1;
        }

        // ---- P -> fp16 A-fragments (register repack) ----
        u32 pa[4][4];
#pragma unroll
        for (int ks = 0; ks < 4; ks++) {
            pa[ks][0] = packh2(s[2*ks][0],   s[2*ks][1]);
            pa[ks][1] = packh2(s[2*ks][2],   s[2*ks][3]);
            pa[ks][2] = packh2(s[2*ks+1][0], s[2*ks+1][1]);
            pa[ks][3] = packh2(s[2*ks+1][2], s[2*ks+1][3]);
        }

        // ---- O += P V  (V via ldmatrix.trans) ----
#pragma unroll
        for (int n = 0; n < 8; n++) {
            u32 vf[8];
            ldsm_x4_t(vf,     stg + OVOF + aswz(lane, n));
            ldsm_x4_t(vf + 4, stg + OVOF + aswz(32 + lane, n));
#pragma unroll
            for (int ks = 0; ks < 4; ks++)
                mma16816h(o[n], pa[ks], vf + 2 * ks);
        }

        __syncthreads();
        if (kb + 2 < nkb) { issueKV(kb + 2, kb & 1); cp_commit(); }
    }

    // ---- epilogue: normalize, emit fp16 into g_Of [B*T, C] ----
    float inv0 = 1.f / l_i0, inv1 = 1.f / l_i1;
    int t0 = qrow0 + m0 + gid;
    size_t rb0 = ((size_t)(b * TT + t0)) * CC + h * DD;
    size_t rb1 = rb0 + (size_t)8 * CC;
#pragma unroll
    for (int n = 0; n < 8; n++) {
        int coff = 8 * n + 2 * tig;
        *(u32*)&g_Of[rb0 + coff] = packh2(o[n][0] * inv0, o[n][1] * inv0);
        *(u32*)&g_Of[rb1 + coff] = packh2(o[n][2] * inv1, o[n][3] * inv1);
    }
}

// ---------------------------------------------------------------------------
extern "C" void kernel_launch(void* const* d_in, const int* in_sizes, int n_in,
                              void* d_out, int out_size)
{
    const float* x     = (const float*)d_in[0];
    // d_in[1] = mask (bool) — causal, applied analytically
    const float* w_qkv = (const float*)d_in[2];
    const float* w_out = (const float*)d_in[3];
    float* out = (float*)d_out;

    // 0) convert all inputs to fp16 (single launch)
    cvt_all<<<(unsigned)((N0 + N1 + N2) / 256), 256>>>(
        (const float4*)x, (const float4*)w_qkv, (const float4*)w_out);

    // 1) QKV projection via fp16 mma.sync -> fp16 Q(scaled)/K/V
    cudaFuncSetAttribute(mma_gemm<0>, cudaFuncAttributeMaxDynamicSharedMemorySize,
                         GSMEM);
    mma_gemm<0><<<dim3(NQKV / 128, MTOT / 128), 256, GSMEM>>>(nullptr);

    // 2) causal flash attention (fp16 mma.sync) -> g_Of
    cudaFuncSetAttribute(flash_attn_fp16,
                         cudaFuncAttributeMaxDynamicSharedMemorySize, ASMEM);
    flash_attn_fp16<<<dim3(TT / QTILE, HH, BB), 256, ASMEM>>>();

    // 3) output projection via fp16 mma.sync -> d_out
    cudaFuncSetAttribute(mma_gemm<1>, cudaFuncAttributeMaxDynamicSharedMemorySize,
                         GSMEM);
    mma_gemm<1><<<dim3(CC / 128, MTOT / 128), 256, GSMEM>>>(out);
}

// round 17
// speedup vs baseline: 7.2516x; 1.0244x over previous
#include <cuda_runtime.h>
#include <cuda_bf16.h>
#include <cuda_fp16.h>
#include <cstdint>
#include <math.h>

// Problem constants
#define BB   4
#define TT   2048
#define CC   1024
#define HH   16
#define DD   64
#define MTOT (BB*TT)          // 8192
#define NQKV (3*CC)           // 3072

typedef unsigned long long u64;
typedef unsigned int u32;

// ---------------------------------------------------------------------------
// Scratch in device globals (no allocations allowed) — all fp16
// ---------------------------------------------------------------------------
__device__ __half g_xf[(size_t)MTOT*CC];
__device__ __half g_wqf[(size_t)NQKV*CC];
__device__ __half g_wof[(size_t)CC*CC];
__device__ __half g_Of[(size_t)MTOT*CC];
__device__ __half g_Qf[(size_t)BB*HH*TT*DD];
__device__ __half g_Kf[(size_t)BB*HH*TT*DD];
__device__ __half g_Vf[(size_t)BB*HH*TT*DD];

// ---------------------------------------------------------------------------
// PTX helpers (plain sm_103 target)
// ---------------------------------------------------------------------------
__device__ __forceinline__ void cp_async16(u32 saddr, const void* gaddr) {
    asm volatile("cp.async.cg.shared.global [%0], [%1], 16;"
                 :: "r"(saddr), "l"(gaddr));
}
__device__ __forceinline__ void cp_commit() {
    asm volatile("cp.async.commit_group;");
}
template<int N>
__device__ __forceinline__ void cp_wait() {
    asm volatile("cp.async.wait_group %0;" :: "n"(N));
}
__device__ __forceinline__ void ldsm_x4(u32* r, u32 addr) {
    asm volatile("ldmatrix.sync.aligned.m8n8.x4.shared.b16 {%0,%1,%2,%3}, [%4];"
                 : "=r"(r[0]), "=r"(r[1]), "=r"(r[2]), "=r"(r[3]) : "r"(addr));
}
__device__ __forceinline__ void ldsm_x4_t(u32* r, u32 addr) {
    asm volatile("ldmatrix.sync.aligned.m8n8.x4.trans.shared.b16 {%0,%1,%2,%3}, [%4];"
                 : "=r"(r[0]), "=r"(r[1]), "=r"(r[2]), "=r"(r[3]) : "r"(addr));
}
__device__ __forceinline__ void mma16816h(float* d, const u32* a, const u32* b) {
    asm volatile(
        "mma.sync.aligned.m16n8k16.row.col.f32.f16.f16.f32 "
        "{%0,%1,%2,%3}, {%4,%5,%6,%7}, {%8,%9}, {%0,%1,%2,%3};"
        : "+f"(d[0]), "+f"(d[1]), "+f"(d[2]), "+f"(d[3])
        : "r"(a[0]), "r"(a[1]), "r"(a[2]), "r"(a[3]), "r"(b[0]), "r"(b[1]));
}
__device__ __forceinline__ u32 packh2(float x, float y) {
    __half2 h = __floats2half2_rn(x, y);   // low=x, high=y
    return *(u32*)&h;
}

// 128B-row swizzle (8 chunks of 16B per row)
__device__ __forceinline__ u32 aswz(int row, int chunk) {
    return (u32)(row * 128 + ((chunk ^ (row & 7)) << 4));
}

// ---------------------------------------------------------------------------
// fp32 -> fp16 conversion, single launch for x, w_qkv, w_out
// ---------------------------------------------------------------------------
#define N0 ((size_t)MTOT*CC/4)
#define N1 ((size_t)NQKV*CC/4)
#define N2 ((size_t)CC*CC/4)

__global__ __launch_bounds__(256)
void cvt_all(const float4* __restrict__ x, const float4* __restrict__ wq,
             const float4* __restrict__ wo)
{
    size_t i = (size_t)blockIdx.x * 256 + threadIdx.x;
    const float4* src;
    uint2* dst;
    size_t j;
    if (i < N0)            { src = x;  dst = (uint2*)g_xf;  j = i; }
    else if (i < N0 + N1)  { src = wq; dst = (uint2*)g_wqf; j = i - N0; }
    else                   { src = wo; dst = (uint2*)g_wof; j = i - N0 - N1; }
    float4 v = src[j];
    uint2 H;
    H.x = packh2(v.x, v.y);
    H.y = packh2(v.z, v.w);
    dst[j] = H;
}

// ---------------------------------------------------------------------------
// mma.sync GEMM (NT), fp16: C[m,n] = sum_k A[m,k]*B[n,k], fp32 acc.
// CTA tile 128x128, 8 warps as 2(wm) x 4(wn) -> 64x32 per warp.
// K-tile 64, 3-stage cp.async ring, one __syncthreads per k-tile.
// Stage: A 16KB @0, B 16KB @16384 (128B rows, aswz swizzle). 96KB smem.
// EPI==0: A=g_xf, B=g_wqf -> g_Qf(*0.125)/g_Kf/g_Vf fp16 [B,H,T,D]
// EPI==1: A=g_Of, B=g_wof -> fp32 row-major Cout
// ---------------------------------------------------------------------------
#define STAGE_BYTES 32768
#define NSTAGE 3
#define GSMEM (NSTAGE * STAGE_BYTES)

template<int EPI>
__global__ __launch_bounds__(256, 2)
void mma_gemm(float* __restrict__ Cout)
{
    extern __shared__ char smem[];
    const u32 sb = (u32)__cvta_generic_to_shared(smem);
    const int tid = threadIdx.x;
    const int wid = tid >> 5, lane = tid & 31;
    const int bn = blockIdx.x, bm = blockIdx.y;

    const __half* A  = EPI ? g_Of  : g_xf;
    const __half* Bw = EPI ? g_wof : g_wqf;

    const int arow = bm * 128, brow = bn * 128;
    const int lrow = tid >> 3, lchunk = tid & 7;   // 32 rows per pass

    auto issue = [&](int kb, int st) {
        const int kcol = kb * 64 + lchunk * 8;
        u32 base = sb + st * STAGE_BYTES;
#pragma unroll
        for (int i = 0; i < 4; i++) {
            int row = lrow + i * 32;
            u32 so = aswz(row, lchunk);
            cp_async16(base + so,         A  + (size_t)(arow + row) * CC + kcol);
            cp_async16(base + 16384 + so, Bw + (size_t)(brow + row) * CC + kcol);
        }
        cp_commit();
    };

    const int wm = wid & 1, wn = wid >> 1;

    // ldmatrix base addresses (stage 0, ks=0)
    u32 aaddr0[4], baddr0[4];
    {
        int mat = lane >> 3, sr = lane & 7;
        int arow_l = wm * 64 + sr + (mat & 1) * 8;
        int achunk = mat >> 1;                // 0/1; ks via ^(ks<<5)
#pragma unroll
        for (int mt = 0; mt < 4; mt++)
            aaddr0[mt] = sb + aswz(arow_l + mt * 16, achunk);
        int brow_l = wn * 32 + (lane & 7);
        int bchunk = lane >> 3;               // 0..3 (k0..31); +4 via ^0x40
#pragma unroll
        for (int nt = 0; nt < 4; nt++)
            baddr0[nt] = sb + 16384 + aswz(brow_l + nt * 8, bchunk);
    }

    float acc[4][4][4];
#pragma unroll
    for (int mt = 0; mt < 4; mt++)
#pragma unroll
        for (int nt = 0; nt < 4; nt++)
#pragma unroll
            for (int e = 0; e < 4; e++) acc[mt][nt][e] = 0.f;

    const int nk = CC / 64;   // 16

    issue(0, 0); issue(1, 1);

    for (int kb = 0; kb < nk; kb++) {
        if (kb == nk - 1) cp_wait<0>(); else cp_wait<1>();
        __syncthreads();

        const u32 soff = (u32)((kb % 3) * STAGE_BYTES);

        // B for the whole k64 tile: 8 chunks per n8 tile
        u32 bfull[4][8];
#pragma unroll
        for (int nt = 0; nt < 4; nt++) {
            u32 bd = baddr0[nt] + soff;
            ldsm_x4(bfull[nt],     bd);
            ldsm_x4(bfull[nt] + 4, bd ^ 0x40u);
        }
        // A per k16 step, reusing a small fragment buffer
#pragma unroll
        for (int ks = 0; ks < 4; ks++) {
            u32 a4[4][4];
#pragma unroll
            for (int mt = 0; mt < 4; mt++)
                ldsm_x4(a4[mt], (aaddr0[mt] + soff) ^ (u32)(ks << 5));
#pragma unroll
            for (int mt = 0; mt < 4; mt++)
#pragma unroll
                for (int nt = 0; nt < 4; nt++)
                    mma16816h(acc[mt][nt], a4[mt], bfull[nt] + 2 * ks);
        }

        // Issue next group AFTER compute: writes stage (kb+2)%3,
        // whose previous readers (iter kb-1) all passed this barrier.
        if (kb + 2 < nk) issue(kb + 2, (kb + 2) % 3);
    }

    const int gid = lane >> 2, tig = lane & 3;
#pragma unroll
    for (int mt = 0; mt < 4; mt++) {
#pragma unroll
        for (int half = 0; half < 2; half++) {
            int m = bm * 128 + wm * 64 + mt * 16 + gid + half * 8;
#pragma unroll
            for (int nt = 0; nt < 4; nt++) {
                float c0 = acc[mt][nt][half * 2 + 0];
                float c1 = acc[mt][nt][half * 2 + 1];
                int n = bn * 128 + wn * 32 + nt * 8 + 2 * tig;
                if (EPI == 0) {
                    int sec = n >> 10, cn = n & 1023;
                    int h = cn >> 6, d = cn & 63;
                    int b = m >> 11, t = m & 2047;
                    size_t idx = (((size_t)(b * HH + h)) * TT + t) * DD + d;
                    __half* dst;
                    if (sec == 0) { c0 *= 0.125f; c1 *= 0.125f; dst = g_Qf; }
                    else if (sec == 1) dst = g_Kf;
                    else               dst = g_Vf;
                    *(u32*)&dst[idx] = packh2(c0, c1);
                } else {
                    *(float2*)&Cout[(size_t)m * CC + n] = make_float2(c0, c1);
                }
            }
        }
    }
}

// ---------------------------------------------------------------------------
// Flash attention (causal) via single-pass fp16 mma.sync.
// CTA: 128-query tile, 8 warps x 16 rows; key blocks of 64, cp.async
// 3-stage K/V ring. Warp-local online softmax. O in fp32.
// smem: Q @0 (16KB), stage s @16K+16K*s: K +0, V +8K. Total 64KB.
// ---------------------------------------------------------------------------
#define QTILE 128
#define KTILE 64
#define ASTG(s) (16384 + (s) * 16384)
#define OKOF 0
#define OVOF 8192
#define ASMEM 65536

__global__ __launch_bounds__(256, 2)
void flash_attn_fp16()
{
    extern __shared__ char smem[];
    const u32 sb = (u32)__cvta_generic_to_shared(smem);
    const int tid = threadIdx.x;
    const int wid = tid >> 5, lane = tid & 31;
    const int b = blockIdx.z, h = blockIdx.y;
    const int qb = gridDim.x - 1 - blockIdx.x;   // heavy tiles first
    const size_t hbase = (size_t)(b * HH + h) * TT * DD;
    const int qrow0 = qb * QTILE;
    const int nkb = 2 * qb + 2;

    // ---- Q tile (fp16): 1024 chunks, 4 per thread ----
#pragma unroll
    for (int i = 0; i < 4; i++) {
        int id = tid + i * 256;
        int row = id >> 3, ch = id & 7;
        cp_async16(sb + aswz(row, ch),
                   g_Qf + hbase + (size_t)(qrow0 + row) * DD + ch * 8);
    }
    // ---- K/V stage issue: 1024 chunks, 4 per thread ----
    auto issueKV = [&](int kb, int st) {
        u32 base = sb + ASTG(st);
        int t0 = kb * KTILE;
#pragma unroll
        for (int i = 0; i < 4; i++) {
            int id = tid + i * 256;
            int tens = id >> 9;              // 0 K, 1 V
            int rem = id & 511;
            int row = rem >> 3, ch = rem & 7;
            const __half* src = tens ? g_Vf : g_Kf;
            u32 off = tens ? OVOF : OKOF;
            cp_async16(base + off + aswz(row, ch),
                       src + hbase + (size_t)(t0 + row) * DD + ch * 8);
        }
        cp_commit();
    };

    issueKV(0, 0);                        // group 0: Q + stage0
    issueKV(1, 1);                        // nkb >= 2 always
    if (nkb > 2) issueKV(2, 2);

    const int m0 = wid * 16;
    const int gid = lane >> 2, tig = lane & 3;
    const int r0g = qrow0 + m0 + gid;
    const int r1g = r0g + 8;

    u32 qf[4][4];
    float o[8][4];
    float m_i0 = -INFINITY, m_i1 = -INFINITY, l_i0 = 0.f, l_i1 = 0.f;
#pragma unroll
    for (int n = 0; n < 8; n++)
#pragma unroll
        for (int e = 0; e < 4; e++) o[n][e] = 0.f;

    for (int kb = 0; kb < nkb; kb++) {
        int rem = nkb - 1 - kb;
        if (rem >= 2)      cp_wait<2>();
        else if (rem == 1) cp_wait<1>();
        else               cp_wait<0>();
        __syncthreads();

        if (kb == 0) {   // load Q fragments once
            int qrow = m0 + (lane & 15);
            int csel = lane >> 4;
#pragma unroll
            for (int ks = 0; ks < 4; ks++)
                ldsm_x4(qf[ks], sb + aswz(qrow, 2 * ks + csel));
        }

        const u32 stg = sb + ASTG(kb % 3);

        // ---- S = Q K^T (16 x 64 per warp) ----
        float s[8][4];
#pragma unroll
        for (int j = 0; j < 8; j++) {
            s[j][0] = s[j][1] = s[j][2] = s[j][3] = 0.f;
            u32 kf[8];
            int krow = 8 * j + (lane & 7);
            int kc = lane >> 3;              // 0..3
            ldsm_x4(kf,     stg + OKOF + aswz(krow, kc));
            ldsm_x4(kf + 4, stg + OKOF + aswz(krow, 4 + kc));
#pragma unroll
            for (int ks = 0; ks < 4; ks++)
                mma16816h(s[j], qf[ks], kf + 2 * ks);
        }

        // ---- causal mask (diagonal-region blocks only) ----
        if (kb >= 2 * qb) {
#pragma unroll
            for (int j = 0; j < 8; j++) {
                int c = kb * KTILE + 8 * j + 2 * tig;
                if (c     > r0g) s[j][0] = -INFINITY;
                if (c + 1 > r0g) s[j][1] = -INFINITY;
                if (c     > r1g) s[j][2] = -INFINITY;
                if (c + 1 > r1g) s[j][3] = -INFINITY;
            }
        }

        // ---- online softmax (rows r0g, r1g; reduce over 4 quad lanes) ----
        float mx0 = -INFINITY, mx1 = -INFINITY;
#pragma unroll
        for (int j = 0; j < 8; j++) {
            mx0 = fmaxf(mx0, fmaxf(s[j][0], s[j][1]));
            mx1 = fmaxf(mx1, fmaxf(s[j][2], s[j][3]));
        }
        mx0 = fmaxf(mx0, __shfl_xor_sync(0xffffffffu, mx0, 1));
        mx0 = fmaxf(mx0, __shfl_xor_sync(0xffffffffu, mx0, 2));
        mx1 = fmaxf(mx1, __shfl_xor_sync(0xffffffffu, mx1, 1));
        mx1 = fmaxf(mx1, __shfl_xor_sync(0xffffffffu, mx1, 2));
        float mn0 = fmaxf(m_i0, mx0), mn1 = fmaxf(m_i1, mx1);
        float al0 = __expf(m_i0 - mn0), al1 = __expf(m_i1 - mn1);
        float sum0 = 0.f, sum1 = 0.f;
#pragma unroll
        for (int j = 0; j < 8; j++) {
            s[j][0] = __expf(s[j][0] - mn0);
            s[j][1] = __expf(s[j][1] - mn0);
            s[j][2] = __expf(s[j][2] - mn1);
            s[j][3] = __expf(s[j][3] - mn1);
            sum0 += s[j][0] + s[j][1];
            sum1 += s[j][2] + s[j][3];
        }
        sum0 += __shfl_xor_sync(0xffffffffu, sum0, 1);
        sum0 += __shfl_xor_sync(0xffffffffu, sum0, 2);
        sum1 += __shfl_xor_sync(0xffffffffu, sum1, 1);
        sum1 += __shfl_xor_sync(0xffffffffu, sum1, 2);
        l_i0 = al0 * l_i0 + sum0;  m_i0 = mn0;
        l_i1 = al1 * l_i1 + sum1;  m_i1 = mn1;
#pragma unroll
        for (int n = 0; n < 8; n++) {
            o[n][0] *= al0; o[n][1] *= al0;
            o[n][2] *= al1; o[n][3] *= al1;
        }

        // ---- P -> fp16 A-fragments (register repack) ----
        u32 pa[4][4];
#pragma unroll
        for (int ks = 0; ks < 4; ks++) {
            pa[ks][0] = packh2(s[2*ks][0],   s[2*ks][1]);
            pa[ks][1] = packh2(s[2*ks][2],   s[2*ks][3]);
            pa[ks][2] = packh2(s[2*ks+1][0], s[2*ks+1][1]);
            pa[ks][3] = packh2(s[2*ks+1][2], s[2*ks+1][3]);
        }

        // ---- O += P V  (V via ldmatrix.trans) ----
#pragma unroll
        for (int n = 0; n < 8; n++) {
            u32 vf[8];
            ldsm_x4_t(vf,     stg + OVOF + aswz(lane, n));
            ldsm_x4_t(vf + 4, stg + OVOF + aswz(32 + lane, n));
#pragma unroll
            for (int ks = 0; ks < 4; ks++)
                mma16816h(o[n], pa[ks], vf + 2 * ks);
        }

        __syncthreads();
        if (kb + 3 < nkb) issueKV(kb + 3, (kb + 3) % 3);
    }

    // ---- epilogue: normalize, emit fp16 into g_Of [B*T, C] ----
    float inv0 = 1.f / l_i0, inv1 = 1.f / l_i1;
    int t0 = qrow0 + m0 + gid;
    size_t rb0 = ((size_t)(b * TT + t0)) * CC + h * DD;
    size_t rb1 = rb0 + (size_t)8 * CC;
#pragma unroll
    for (int n = 0; n < 8; n++) {
        int coff = 8 * n + 2 * tig;
        *(u32*)&g_Of[rb0 + coff] = packh2(o[n][0] * inv0, o[n][1] * inv0);
        *(u32*)&g_Of[rb1 + coff] = packh2(o[n][2] * inv1, o[n][3] * inv1);
    }
}

// ---------------------------------------------------------------------------
extern "C" void kernel_launch(void* const* d_in, const int* in_sizes, int n_in,
                              void* d_out, int out_size)
{
    const float* x     = (const float*)d_in[0];
    // d_in[1] = mask (bool) — causal, applied analytically
    const float* w_qkv = (const float*)d_in[2];
    const float* w_out = (const float*)d_in[3];
    float* out = (float*)d_out;

    // 0) convert all inputs to fp16 (single launch)
    cvt_all<<<(unsigned)((N0 + N1 + N2) / 256), 256>>>(
        (const float4*)x, (const float4*)w_qkv, (const float4*)w_out);

    // 1) QKV projection via fp16 mma.sync -> fp16 Q(scaled)/K/V
    cudaFuncSetAttribute(mma_gemm<0>, cudaFuncAttributeMaxDynamicSharedMemorySize,
                         GSMEM);
    mma_gemm<0><<<dim3(NQKV / 128, MTOT / 128), 256, GSMEM>>>(nullptr);

    // 2) causal flash attention (fp16 mma.sync) -> g_Of
    cudaFuncSetAttribute(flash_attn_fp16,
                         cudaFuncAttributeMaxDynamicSharedMemorySize, ASMEM);
    flash_attn_fp16<<<dim3(TT / QTILE, HH, BB), 256, ASMEM>>>();

    // 3) output projection via fp16 mma.sync -> d_out
    cudaFuncSetAttribute(mma_gemm<1>, cudaFuncAttributeMaxDynamicSharedMemorySize,
                         GSMEM);
    mma_gemm<1><<<dim3(CC / 128, MTOT / 128), 256, GSMEM>>>(out);
}